// round 1
// baseline (speedup 1.0000x reference)
#include <cuda_runtime.h>
#include <cuda_bf16.h>
#include <math.h>

// Problem constants
#define BB 2
#define LL 1024
#define DM 768
#define NS 16
#define KC 4
#define DR 48
#define ML (BB*LL)          // 2048 rows
#define XPW (DR + 2*NS)     // 80

// Scratch (device globals; allocation is forbidden)
__device__ float g_xs0[ML*DM];    // pre-conv xs
__device__ float g_sres[ML*DM];   // silu(res)
__device__ float g_u[ML*DM];      // post conv+silu
__device__ float g_xp[ML*XPW];    // delta_r | B | C
__device__ float g_delta[ML*DM];  // softplus-clipped delta
__device__ float g_y[ML*DM];      // gated scan output

__device__ __forceinline__ float silu_f(float x) {
    return x / (1.0f + __expf(-x));
}

// ---------------------------------------------------------------------------
// SGEMM: C = A(MxK, lda) * B(KxN, ldb), fp32, BM=BN=128, BK=16, 256 threads,
// 8x8 per-thread tile. Requires M%128==0, K%16==0 (true for all calls here).
// EPI 0: plain store (ldc=N). EPI 1: split cols [0,768)->C0, [768,1536)->silu->C1.
// EPI 2: +bias, softplus, clip [1e-4,0.1] -> C0.
// ---------------------------------------------------------------------------
#define Bb_M 128
#define Bb_N 128
#define Bb_K 16

template<int EPI>
__global__ __launch_bounds__(256)
void sgemm_k(const float* __restrict__ A, const float* __restrict__ B,
             const float* __restrict__ bias,
             float* __restrict__ C0, float* __restrict__ C1,
             int M, int N, int K, int lda, int ldb) {
    __shared__ float As[Bb_K][Bb_M + 4];
    __shared__ float Bs[Bb_K][Bb_N];

    const int tid = threadIdx.x;
    const int bm = blockIdx.x * Bb_M;
    const int bn = blockIdx.y * Bb_N;
    const int tx = tid & 15;
    const int ty = tid >> 4;

    float acc[8][8];
#pragma unroll
    for (int i = 0; i < 8; i++)
#pragma unroll
        for (int j = 0; j < 8; j++) acc[i][j] = 0.f;

    for (int k0 = 0; k0 < K; k0 += Bb_K) {
        // Load A tile (128 x 16) as 512 float4, transpose into As[k][m]
#pragma unroll
        for (int it = 0; it < 2; it++) {
            int v = tid + it * 256;
            int m = v >> 2;
            int kq = (v & 3) * 4;
            float4 a = *(const float4*)(A + (size_t)(bm + m) * lda + k0 + kq);
            As[kq + 0][m] = a.x;
            As[kq + 1][m] = a.y;
            As[kq + 2][m] = a.z;
            As[kq + 3][m] = a.w;
        }
        // Load B tile (16 x 128) as 512 float4
#pragma unroll
        for (int it = 0; it < 2; it++) {
            int v = tid + it * 256;
            int kk = v >> 5;
            int n0 = (v & 31) * 4;
            float4 bv;
            if (bn + n0 + 3 < N)
                bv = *(const float4*)(B + (size_t)(k0 + kk) * ldb + bn + n0);
            else
                bv = make_float4(0.f, 0.f, 0.f, 0.f);
            *(float4*)(&Bs[kk][n0]) = bv;
        }
        __syncthreads();

#pragma unroll
        for (int k = 0; k < Bb_K; k++) {
            float a[8], b[8];
            *(float4*)(a)     = *(const float4*)(&As[k][ty * 8]);
            *(float4*)(a + 4) = *(const float4*)(&As[k][ty * 8 + 4]);
            *(float4*)(b)     = *(const float4*)(&Bs[k][tx * 8]);
            *(float4*)(b + 4) = *(const float4*)(&Bs[k][tx * 8 + 4]);
#pragma unroll
            for (int i = 0; i < 8; i++)
#pragma unroll
                for (int j = 0; j < 8; j++)
                    acc[i][j] = fmaf(a[i], b[j], acc[i][j]);
        }
        __syncthreads();
    }

    // Epilogue
#pragma unroll
    for (int i = 0; i < 8; i++) {
        int row = bm + ty * 8 + i;
#pragma unroll
        for (int j = 0; j < 8; j++) {
            int col = bn + tx * 8 + j;
            if (col >= N) continue;
            float v = acc[i][j];
            if (EPI == 0) {
                C0[(size_t)row * N + col] = v;
            } else if (EPI == 1) {
                if (col < DM) C0[(size_t)row * DM + col] = v;
                else          C1[(size_t)row * DM + (col - DM)] = silu_f(v);
            } else {
                v += bias[col];
                float sp = (v > 0.f) ? (v + log1pf(__expf(-v))) : log1pf(__expf(v));
                sp = fminf(fmaxf(sp, 1e-4f), 0.1f);
                C0[(size_t)row * N + col] = sp;
            }
        }
    }
}

// ---------------------------------------------------------------------------
// Depthwise causal conv (K=4) + bias + SiLU:  g_xs0 -> g_u
// ---------------------------------------------------------------------------
__global__ __launch_bounds__(256)
void conv_silu_kernel(const float* __restrict__ conv_w, const float* __restrict__ conv_b) {
    int idx = blockIdx.x * blockDim.x + threadIdx.x;
    if (idx >= ML * DM) return;
    int d = idx % DM;
    int t = (idx / DM) % LL;
    int base = idx - t * DM - d;   // b*L*D
    float acc = conv_b[d];
#pragma unroll
    for (int k = 0; k < KC; k++) {
        int tt = t - (KC - 1) + k;
        if (tt >= 0)
            acc = fmaf(conv_w[d * KC + k], g_xs0[base + tt * DM + d], acc);
    }
    g_u[idx] = silu_f(acc);
}

// ---------------------------------------------------------------------------
// Selective scan. One 16-lane half-warp per (b,d); lane = state index n.
// Replicates the reference's exact formula:
//   cs_t = T - P_t (T = A_n * sum_t delta_t, P_t = running prefix incl. t)
//   num_t = cumsum(delta*u*B * exp(cs));  xs_t = num_t / (exp(cs_t)+1e-12)
//   y_t = (sum_n xs_t * C_t[n] + u_t * D[d]) * silu(res)
// fp32 underflow of exp(cs) matches the reference's behavior.
// ---------------------------------------------------------------------------
__global__ __launch_bounds__(128)
void scan_kernel(const float* __restrict__ A_log, const float* __restrict__ D_param) {
    int lane = threadIdx.x & 31;
    int warp = blockIdx.x * (blockDim.x >> 5) + (threadIdx.x >> 5);
    int half = lane >> 4;
    int ln = lane & 15;                 // state index n
    int p = warp * 2 + half;            // (b,d) pair index, 0..1535
    if (p >= BB * DM) return;
    int b = p / DM;
    int d = p % DM;

    const float* dptr = g_delta + (size_t)b * LL * DM + d;
    const float* uptr = g_u     + (size_t)b * LL * DM + d;
    const float* srp  = g_sres  + (size_t)b * LL * DM + d;
    const float* xpB  = g_xp    + (size_t)b * LL * XPW + DR + ln;  // B at +0, C at +NS
    float* yp = g_y + (size_t)b * LL * DM + d;

    // Deterministic in-warp total: Sdelta = sum_t delta[b,t,d]
    float s = 0.f;
#pragma unroll 4
    for (int i = 0; i < LL / 16; i++)
        s += dptr[(size_t)(ln + i * 16) * DM];
#pragma unroll
    for (int o = 8; o > 0; o >>= 1)
        s += __shfl_xor_sync(0xffffffffu, s, o, 16);

    float An = -__expf(A_log[d * NS + ln]);
    float T = An * s;
    float Dp = D_param[d];

    float P = 0.f, num = 0.f;
    for (int t = 0; t < LL; t++) {
        float delta = dptr[(size_t)t * DM];
        float u     = uptr[(size_t)t * DM];
        float Bv    = xpB[(size_t)t * XPW];
        float Cv    = xpB[(size_t)t * XPW + NS];

        P = fmaf(delta, An, P);
        float e = __expf(T - P);
        num = fmaf(delta * u * Bv, e, num);
        float x = num / (e + 1e-12f);
        float c = x * Cv;
#pragma unroll
        for (int o = 8; o > 0; o >>= 1)
            c += __shfl_xor_sync(0xffffffffu, c, o, 16);
        if (ln == 0) {
            float y = fmaf(u, Dp, c);
            yp[(size_t)t * DM] = y * srp[(size_t)t * DM];
        }
    }
}

// ---------------------------------------------------------------------------
// Launch
// ---------------------------------------------------------------------------
extern "C" void kernel_launch(void* const* d_in, const int* in_sizes, int n_in,
                              void* d_out, int out_size) {
    const float* x       = (const float*)d_in[0];
    const float* W_in    = (const float*)d_in[1];
    const float* conv_w  = (const float*)d_in[2];
    const float* conv_b  = (const float*)d_in[3];
    const float* W_x     = (const float*)d_in[4];
    const float* W_delta = (const float*)d_in[5];
    const float* b_delta = (const float*)d_in[6];
    const float* A_log   = (const float*)d_in[7];
    const float* D_param = (const float*)d_in[8];
    const float* W_out   = (const float*)d_in[9];
    float* out = (float*)d_out;

    float* p_xs0, *p_sres, *p_u, *p_xp, *p_delta, *p_y;
    cudaGetSymbolAddress((void**)&p_xs0,   g_xs0);
    cudaGetSymbolAddress((void**)&p_sres,  g_sres);
    cudaGetSymbolAddress((void**)&p_u,     g_u);
    cudaGetSymbolAddress((void**)&p_xp,    g_xp);
    cudaGetSymbolAddress((void**)&p_delta, g_delta);
    cudaGetSymbolAddress((void**)&p_y,     g_y);

    // 1) xr = x @ W_in ; split -> g_xs0 (raw), g_sres (silu)
    {
        dim3 grid(ML / Bb_M, (2 * DM + Bb_N - 1) / Bb_N);
        sgemm_k<1><<<grid, 256>>>(x, W_in, nullptr, p_xs0, p_sres,
                                  ML, 2 * DM, DM, DM, 2 * DM);
    }
    // 2) depthwise causal conv + silu -> g_u
    conv_silu_kernel<<<(ML * DM + 255) / 256, 256>>>(conv_w, conv_b);
    // 3) xp = u @ W_x  (N=80)
    {
        dim3 grid(ML / Bb_M, (XPW + Bb_N - 1) / Bb_N);
        sgemm_k<0><<<grid, 256>>>(p_u, W_x, nullptr, p_xp, nullptr,
                                  ML, XPW, DM, DM, XPW);
    }
    // 4) delta = clip(softplus(xp[:, :48] @ W_delta + b_delta))
    {
        dim3 grid(ML / Bb_M, (DM + Bb_N - 1) / Bb_N);
        sgemm_k<2><<<grid, 256>>>(p_xp, W_delta, b_delta, p_delta, nullptr,
                                  ML, DM, DR, XPW, DM);
    }
    // 5) selective scan + gate -> g_y
    scan_kernel<<<(BB * DM / 2 + 3) / 4, 128>>>(A_log, D_param);
    // 6) out = y @ W_out
    {
        dim3 grid(ML / Bb_M, (DM + Bb_N - 1) / Bb_N);
        sgemm_k<0><<<grid, 256>>>(p_y, W_out, nullptr, out, nullptr,
                                  ML, DM, DM, DM, DM);
    }
}

// round 2
// speedup vs baseline: 2.6922x; 2.6922x over previous
#include <cuda_runtime.h>
#include <cuda_bf16.h>
#include <math.h>

#define BB 2
#define LL 1024
#define DM 768
#define NS 16
#define KC 4
#define DR 48
#define ML (BB*LL)          // 2048 rows
#define XPW (DR + 2*NS)     // 80

// Scratch
__device__ float g_xs0[ML*DM];
__device__ float g_sres[ML*DM];
__device__ float g_u[ML*DM];
__device__ float g_xp[ML*XPW];
__device__ float g_delta[ML*DM];
__device__ float g_y[ML*DM];
__device__ float g_deltaT[ML*DM];     // (b,d,t)
__device__ float g_duT[ML*DM];        // (b,d,t) of delta*u
__device__ float g_yT[ML*DM];         // (b,d,t) scan output (sum_n x*C only)
__device__ float g_bcT[BB*2*NS*LL];   // (b, ch, t), ch: 0..15 = B states, 16..31 = C states
__device__ float g_p1[2*ML*2*DM];     // split-K partials for gemm1
__device__ float g_po[2*ML*DM];       // split-K partials for gemm_out
__device__ float g_xpp[8*ML*XPW];     // split-K partials for gemm_x

__device__ __forceinline__ float silu_f(float x) {
    return x / (1.0f + __expf(-x));
}

// ---------------------------------------------------------------------------
// Pipelined SGEMM: C = A(MxK,lda) * B(KxN,ldb). 128x128x16 tiles, 256 thr,
// 8x8/thread, double-buffered smem + register prefetch, 1 sync/tile.
// gridDim.z>1 -> split-K: chunk kspl, partial z stored at C0 + z*M*N.
// EPI 0: plain float4 store. EPI 2: +bias, softplus, clip.
// ---------------------------------------------------------------------------
#define Bb_M 128
#define Bb_N 128
#define Bb_K 16

template<int EPI>
__global__ __launch_bounds__(256, 2)
void sgemm_pipe(const float* __restrict__ A, const float* __restrict__ B,
                const float* __restrict__ bias,
                float* __restrict__ C0,
                int M, int N, int K, int lda, int ldb, int kspl) {
    __shared__ float As[2][Bb_K][Bb_M + 4];
    __shared__ float Bs[2][Bb_K][Bb_N];

    const int tid = threadIdx.x;
    const int bm = blockIdx.x * Bb_M;
    const int bn = blockIdx.y * Bb_N;
    const int tx = tid & 15;
    const int ty = tid >> 4;

    const float* Ap = A;
    const float* Bp = B;
    float* Cp = C0;
    int kcnt = K;
    if (gridDim.z > 1) {
        kcnt = kspl;
        Ap += (size_t)blockIdx.z * kspl;
        Bp += (size_t)blockIdx.z * kspl * ldb;
        Cp += (size_t)blockIdx.z * M * N;
    }

    const int am0 = tid >> 2;           // 0..63, +64 for 2nd
    const int ak  = (tid & 3) * 4;
    const int bk0 = tid >> 5;           // 0..7, +8 for 2nd
    const int bn0 = (tid & 31) * 4;
    const bool bok = (bn + bn0 + 3) < N;

    float4 ra0, ra1, rb0, rb1;

    float acc[8][8];
#pragma unroll
    for (int i = 0; i < 8; i++)
#pragma unroll
        for (int j = 0; j < 8; j++) acc[i][j] = 0.f;

    // prologue: tile 0
    {
        ra0 = *(const float4*)(Ap + (size_t)(bm + am0)      * lda + ak);
        ra1 = *(const float4*)(Ap + (size_t)(bm + am0 + 64) * lda + ak);
        rb0 = bok ? *(const float4*)(Bp + (size_t)(bk0)     * ldb + bn + bn0) : make_float4(0.f,0.f,0.f,0.f);
        rb1 = bok ? *(const float4*)(Bp + (size_t)(bk0 + 8) * ldb + bn + bn0) : make_float4(0.f,0.f,0.f,0.f);
        As[0][ak+0][am0] = ra0.x; As[0][ak+1][am0] = ra0.y; As[0][ak+2][am0] = ra0.z; As[0][ak+3][am0] = ra0.w;
        As[0][ak+0][am0+64] = ra1.x; As[0][ak+1][am0+64] = ra1.y; As[0][ak+2][am0+64] = ra1.z; As[0][ak+3][am0+64] = ra1.w;
        *(float4*)(&Bs[0][bk0][bn0]) = rb0;
        *(float4*)(&Bs[0][bk0+8][bn0]) = rb1;
    }
    __syncthreads();

    const int nt = kcnt / Bb_K;
    for (int t = 0; t < nt; t++) {
        const int cur = t & 1;
        const int k0n = (t + 1) * Bb_K;
        if (t + 1 < nt) {
            ra0 = *(const float4*)(Ap + (size_t)(bm + am0)      * lda + k0n + ak);
            ra1 = *(const float4*)(Ap + (size_t)(bm + am0 + 64) * lda + k0n + ak);
            rb0 = bok ? *(const float4*)(Bp + (size_t)(k0n + bk0)     * ldb + bn + bn0) : make_float4(0.f,0.f,0.f,0.f);
            rb1 = bok ? *(const float4*)(Bp + (size_t)(k0n + bk0 + 8) * ldb + bn + bn0) : make_float4(0.f,0.f,0.f,0.f);
        }
#pragma unroll
        for (int k = 0; k < Bb_K; k++) {
            float a[8], b[8];
            *(float4*)(a)     = *(const float4*)(&As[cur][k][ty * 8]);
            *(float4*)(a + 4) = *(const float4*)(&As[cur][k][ty * 8 + 4]);
            *(float4*)(b)     = *(const float4*)(&Bs[cur][k][tx * 8]);
            *(float4*)(b + 4) = *(const float4*)(&Bs[cur][k][tx * 8 + 4]);
#pragma unroll
            for (int i = 0; i < 8; i++)
#pragma unroll
                for (int j = 0; j < 8; j++)
                    acc[i][j] = fmaf(a[i], b[j], acc[i][j]);
        }
        if (t + 1 < nt) {
            const int nxt = cur ^ 1;
            As[nxt][ak+0][am0] = ra0.x; As[nxt][ak+1][am0] = ra0.y; As[nxt][ak+2][am0] = ra0.z; As[nxt][ak+3][am0] = ra0.w;
            As[nxt][ak+0][am0+64] = ra1.x; As[nxt][ak+1][am0+64] = ra1.y; As[nxt][ak+2][am0+64] = ra1.z; As[nxt][ak+3][am0+64] = ra1.w;
            *(float4*)(&Bs[nxt][bk0][bn0]) = rb0;
            *(float4*)(&Bs[nxt][bk0+8][bn0]) = rb1;
        }
        __syncthreads();
    }

    // epilogue (N always multiple of 4; thread col groups never straddle N)
#pragma unroll
    for (int i = 0; i < 8; i++) {
        const int row = bm + ty * 8 + i;
#pragma unroll
        for (int jj = 0; jj < 8; jj += 4) {
            const int col = bn + tx * 8 + jj;
            if (col >= N) continue;
            if (EPI == 0) {
                *(float4*)(&Cp[(size_t)row * N + col]) =
                    make_float4(acc[i][jj], acc[i][jj+1], acc[i][jj+2], acc[i][jj+3]);
            } else {
                float o[4];
#pragma unroll
                for (int q = 0; q < 4; q++) {
                    float v = acc[i][jj+q] + bias[col+q];
                    float sp = (v > 0.f) ? (v + log1pf(__expf(-v))) : log1pf(__expf(v));
                    o[q] = fminf(fmaxf(sp, 1e-4f), 0.1f);
                }
                *(float4*)(&Cp[(size_t)row * N + col]) = make_float4(o[0], o[1], o[2], o[3]);
            }
        }
    }
}

// ---------------------------------------------------------------------------
// Split-K reduce kernels
// ---------------------------------------------------------------------------
__global__ __launch_bounds__(256)
void reduce_gemm1_kernel() {   // p1 (2 partials of ML x 2DM) -> xs0 | silu->sres
    int i4 = blockIdx.x * blockDim.x + threadIdx.x;   // float4 index
    const float4* pa = (const float4*)g_p1;
    const float4* pb = (const float4*)(g_p1 + (size_t)ML * 2 * DM);
    float4 a = pa[i4], b = pb[i4];
    float4 s = make_float4(a.x+b.x, a.y+b.y, a.z+b.z, a.w+b.w);
    int col = (i4 * 4) % (2 * DM);
    int row = (i4 * 4) / (2 * DM);
    if (col < DM) {
        *(float4*)(&g_xs0[(size_t)row * DM + col]) = s;
    } else {
        float4 o = make_float4(silu_f(s.x), silu_f(s.y), silu_f(s.z), silu_f(s.w));
        *(float4*)(&g_sres[(size_t)row * DM + (col - DM)]) = o;
    }
}

__global__ __launch_bounds__(256)
void reduce_out_kernel(float* __restrict__ out) {
    int i4 = blockIdx.x * blockDim.x + threadIdx.x;
    const float4* pa = (const float4*)g_po;
    const float4* pb = (const float4*)(g_po + (size_t)ML * DM);
    float4 a = pa[i4], b = pb[i4];
    ((float4*)out)[i4] = make_float4(a.x+b.x, a.y+b.y, a.z+b.z, a.w+b.w);
}

__global__ __launch_bounds__(256)
void reduce_xp_kernel() {   // 8 partials -> g_xp; cols 48..79 also scattered to g_bcT
    int idx = blockIdx.x * blockDim.x + threadIdx.x;  // < ML*XPW
    float s = 0.f;
#pragma unroll
    for (int z = 0; z < 8; z++) s += g_xpp[(size_t)z * ML * XPW + idx];
    g_xp[idx] = s;
    int c = idx % XPW;
    int r = idx / XPW;
    if (c >= DR) {
        int b = r / LL, t = r % LL;
        g_bcT[((size_t)b * 2 * NS + (c - DR)) * LL + t] = s;
    }
}

// ---------------------------------------------------------------------------
// Depthwise causal conv (K=4) + bias + SiLU:  g_xs0 -> g_u
// ---------------------------------------------------------------------------
__global__ __launch_bounds__(256)
void conv_silu_kernel(const float* __restrict__ conv_w, const float* __restrict__ conv_b) {
    int idx = blockIdx.x * blockDim.x + threadIdx.x;
    if (idx >= ML * DM) return;
    int d = idx % DM;
    int t = (idx / DM) % LL;
    int base = idx - t * DM - d;
    float acc = conv_b[d];
#pragma unroll
    for (int k = 0; k < KC; k++) {
        int tt = t - (KC - 1) + k;
        if (tt >= 0)
            acc = fmaf(conv_w[d * KC + k], g_xs0[base + tt * DM + d], acc);
    }
    g_u[idx] = silu_f(acc);
}

// ---------------------------------------------------------------------------
// Transpose fwd: (b,t,d) -> (b,d,t) for delta and delta*u. 32x32 tiles.
// grid (ML/32, DM/32), block (32,8)
// ---------------------------------------------------------------------------
__global__ __launch_bounds__(256)
void trans_fwd_kernel() {
    __shared__ float t0[32][33];
    __shared__ float t1[32][33];
    const int r0 = blockIdx.x * 32;       // row base in ML (never crosses b)
    const int d0 = blockIdx.y * 32;
    const int b  = r0 / LL;
    const int tb = r0 % LL;
#pragma unroll
    for (int j = 0; j < 4; j++) {
        int row = r0 + threadIdx.y + j * 8;
        int d = d0 + threadIdx.x;
        float dl = g_delta[(size_t)row * DM + d];
        float uu = g_u[(size_t)row * DM + d];
        t0[threadIdx.y + j * 8][threadIdx.x] = dl;
        t1[threadIdx.y + j * 8][threadIdx.x] = dl * uu;
    }
    __syncthreads();
#pragma unroll
    for (int j = 0; j < 4; j++) {
        int d = d0 + threadIdx.y + j * 8;
        int t = tb + threadIdx.x;
        g_deltaT[((size_t)b * DM + d) * LL + t] = t0[threadIdx.x][threadIdx.y + j * 8];
        g_duT   [((size_t)b * DM + d) * LL + t] = t1[threadIdx.x][threadIdx.y + j * 8];
    }
}

// ---------------------------------------------------------------------------
// Parallel selective scan. One block per (b,d). 256 thr = 8 warps.
// Phase 1: block prefix-sum of delta -> pd[], total S.
// Phase 2: warp w handles states w and w+8: chunked warp prefix scans of
//          z_t = du_t * B_t[n] * exp(An*(S-pd_t)); x_t = num_t/(e_t+1e-12);
//          accumulate x*C into warp-private smem row (deterministic).
// Phase 3: reduce 8 rows -> g_yT (b,d,t).
// ---------------------------------------------------------------------------
__global__ __launch_bounds__(256)
void scan_par_kernel(const float* __restrict__ A_log) {
    __shared__ float pd[LL];
    __shared__ float du[LL];
    __shared__ float ysw[8][LL];
    __shared__ float wsum[9];

    const int bd = blockIdx.x;
    const int b = bd / DM, d = bd - b * DM;
    const int tid = threadIdx.x, lane = tid & 31, wrp = tid >> 5;

    const float* dT  = g_deltaT + (size_t)bd * LL;
    const float* duT = g_duT    + (size_t)bd * LL;

    float4 v = ((const float4*)dT)[tid];
    ((float4*)du)[tid] = ((const float4*)duT)[tid];
    float s0 = v.x, s1 = s0 + v.y, s2 = s1 + v.z, s3 = s2 + v.w;
    float ts = s3;
#pragma unroll
    for (int o = 1; o < 32; o <<= 1) {
        float nv = __shfl_up_sync(0xffffffffu, ts, o);
        if (lane >= o) ts += nv;
    }
    if (lane == 31) wsum[wrp] = ts;
    // zero warp-private accumulation row
#pragma unroll
    for (int k = 0; k < LL / 32 / 4; k++)
        ((float4*)ysw[wrp])[lane + k * 32] = make_float4(0.f, 0.f, 0.f, 0.f);
    __syncthreads();
    if (tid == 0) {
        float a = 0.f;
#pragma unroll
        for (int i = 0; i < 8; i++) { float x = wsum[i]; wsum[i] = a; a += x; }
        wsum[8] = a;
    }
    __syncthreads();
    float base = wsum[wrp] + ts - s3;
    pd[tid * 4 + 0] = base + s0;
    pd[tid * 4 + 1] = base + s1;
    pd[tid * 4 + 2] = base + s2;
    pd[tid * 4 + 3] = base + s3;
    const float S = wsum[8];
    __syncthreads();

#pragma unroll
    for (int sp = 0; sp < 2; sp++) {
        const int n = wrp + sp * 8;
        const float An = -__expf(A_log[d * NS + n]);
        const float* Bn = g_bcT + ((size_t)b * 2 * NS + n) * LL;
        const float* Cn = g_bcT + ((size_t)b * 2 * NS + NS + n) * LL;
        float carry = 0.f;
        for (int j = 0; j < 32; j++) {
            const int t = j * 32 + lane;
            float e = __expf(An * (S - pd[t]));
            float z = du[t] * Bn[t] * e;
            float sc = z;
#pragma unroll
            for (int o = 1; o < 32; o <<= 1) {
                float nv = __shfl_up_sync(0xffffffffu, sc, o);
                if (lane >= o) sc += nv;
            }
            float num = carry + sc;
            carry = __shfl_sync(0xffffffffu, num, 31);
            float x = num / (e + 1e-12f);
            ysw[wrp][t] += x * Cn[t];
        }
    }
    __syncthreads();

    float4 r = ((const float4*)ysw[0])[tid];
#pragma unroll
    for (int w = 1; w < 8; w++) {
        float4 q = ((const float4*)ysw[w])[tid];
        r.x += q.x; r.y += q.y; r.z += q.z; r.w += q.w;
    }
    ((float4*)(g_yT + (size_t)bd * LL))[tid] = r;
}

// ---------------------------------------------------------------------------
// Transpose back + epilogue: y[b,t,d] = (yT[b,d,t] + u*Dp) * sres
// grid (ML/32, DM/32), block (32,8)
// ---------------------------------------------------------------------------
__global__ __launch_bounds__(256)
void back_gate_kernel(const float* __restrict__ D_param) {
    __shared__ float tl[32][33];
    const int r0 = blockIdx.x * 32;
    const int d0 = blockIdx.y * 32;
    const int b  = r0 / LL;
    const int tb = r0 % LL;
#pragma unroll
    for (int j = 0; j < 4; j++) {
        int d = d0 + threadIdx.y + j * 8;
        tl[threadIdx.y + j * 8][threadIdx.x] =
            g_yT[((size_t)b * DM + d) * LL + tb + threadIdx.x];
    }
    __syncthreads();
#pragma unroll
    for (int j = 0; j < 4; j++) {
        int row = r0 + threadIdx.y + j * 8;
        int d = d0 + threadIdx.x;
        float v = tl[threadIdx.x][threadIdx.y + j * 8];
        float uu = g_u[(size_t)row * DM + d];
        float sr = g_sres[(size_t)row * DM + d];
        g_y[(size_t)row * DM + d] = (v + uu * D_param[d]) * sr;
    }
}

// ---------------------------------------------------------------------------
extern "C" void kernel_launch(void* const* d_in, const int* in_sizes, int n_in,
                              void* d_out, int out_size) {
    const float* x       = (const float*)d_in[0];
    const float* W_in    = (const float*)d_in[1];
    const float* conv_w  = (const float*)d_in[2];
    const float* conv_b  = (const float*)d_in[3];
    const float* W_x     = (const float*)d_in[4];
    const float* W_delta = (const float*)d_in[5];
    const float* b_delta = (const float*)d_in[6];
    const float* A_log   = (const float*)d_in[7];
    const float* D_param = (const float*)d_in[8];
    const float* W_out   = (const float*)d_in[9];
    float* out = (float*)d_out;

    float *p_xp, *p_delta, *p_y, *p_p1, *p_po, *p_xpp, *p_u;
    cudaGetSymbolAddress((void**)&p_xp,    g_xp);
    cudaGetSymbolAddress((void**)&p_delta, g_delta);
    cudaGetSymbolAddress((void**)&p_y,     g_y);
    cudaGetSymbolAddress((void**)&p_p1,    g_p1);
    cudaGetSymbolAddress((void**)&p_po,    g_po);
    cudaGetSymbolAddress((void**)&p_xpp,   g_xpp);
    cudaGetSymbolAddress((void**)&p_u,     g_u);

    // 1) gemm1 partials: x(2048x768) @ W_in(768x1536), split-K=2
    {
        dim3 grid(ML / Bb_M, (2 * DM) / Bb_N, 2);
        sgemm_pipe<0><<<grid, 256>>>(x, W_in, nullptr, p_p1,
                                     ML, 2 * DM, DM, DM, 2 * DM, DM / 2);
    }
    // 2) reduce -> xs0, silu->sres
    reduce_gemm1_kernel<<<(ML * 2 * DM / 4) / 256, 256>>>();
    // 3) conv + silu -> u
    conv_silu_kernel<<<(ML * DM + 255) / 256, 256>>>(conv_w, conv_b);
    // 4) gemm_x partials: u @ W_x (768x80), split-K=8
    {
        dim3 grid(ML / Bb_M, 1, 8);
        sgemm_pipe<0><<<grid, 256>>>(p_u, W_x, nullptr, p_xpp,
                                     ML, XPW, DM, DM, XPW, DM / 8);
    }
    // 5) reduce -> xp + bcT scatter
    reduce_xp_kernel<<<(ML * XPW) / 256, 256>>>();
    // 6) delta gemm: xp[:, :48] @ W_delta(48x768) + softplus/clip
    {
        dim3 grid(ML / Bb_M, DM / Bb_N, 1);
        sgemm_pipe<2><<<grid, 256>>>(p_xp, W_delta, b_delta, p_delta,
                                     ML, DM, DR, XPW, DM, DR);
    }
    // 7) transpose delta, delta*u -> (b,d,t)
    {
        dim3 grid(ML / 32, DM / 32);
        trans_fwd_kernel<<<grid, dim3(32, 8)>>>();
    }
    // 8) parallel scan -> yT
    scan_par_kernel<<<BB * DM, 256>>>(A_log);
    // 9) transpose back + u*Dp + gate -> y
    {
        dim3 grid(ML / 32, DM / 32);
        back_gate_kernel<<<grid, dim3(32, 8)>>>(D_param);
    }
    // 10) out gemm partials: y @ W_out(768x768), split-K=2
    {
        dim3 grid(ML / Bb_M, DM / Bb_N, 2);
        sgemm_pipe<0><<<grid, 256>>>(p_y, W_out, nullptr, p_po,
                                     ML, DM, DM, DM, DM, DM / 2);
    }
    // 11) reduce -> out
    reduce_out_kernel<<<(ML * DM / 4) / 256, 256>>>(out);
}

// round 4
// speedup vs baseline: 3.7249x; 1.3836x over previous
#include <cuda_runtime.h>
#include <cuda_bf16.h>
#include <cstdint>
#include <math.h>

#define BB 2
#define LL 1024
#define DM 768
#define NS 16
#define KC 4
#define DR 48
#define ML (BB*LL)          // 2048 rows
#define XPW (DR + 2*NS)     // 80

// ---------------- scratch (device globals; allocation forbidden) ----------
__device__ float g_xs0[ML*DM];
__device__ float g_sres[ML*DM];
__device__ float g_u[ML*DM];
__device__ float g_xp[ML*XPW];
__device__ float g_delta[ML*DM];
__device__ float g_deltaT[ML*DM];     // (b,d,t)
__device__ float g_duT[ML*DM];        // (b,d,t) delta*u
__device__ float g_yT[ML*DM];         // (b,d,t) scan out
__device__ float g_bcT[BB*2*NS*LL];
__device__ float g_xpp[8*ML*XPW];     // split-K partials for gemm_x

// bf16 hi/lo operands for tensor GEMMs
__device__ __nv_bfloat16 g_xhi[ML*DM],  g_xlo[ML*DM];      // x split, [M][K]
__device__ __nv_bfloat16 g_yhi[ML*DM],  g_ylo[ML*DM];      // y split, [M][K]
__device__ __nv_bfloat16 g_wihi[2*DM*DM], g_wilo[2*DM*DM]; // W_in^T  [1536][768]
__device__ __nv_bfloat16 g_wohi[DM*DM],   g_wolo[DM*DM];   // W_out^T [768][768]

__device__ __forceinline__ float silu_f(float x) {
    return x / (1.0f + __expf(-x));
}

__device__ __forceinline__ uint32_t smem_u32(const void* p) {
    uint32_t a;
    asm("{ .reg .u64 t; cvta.to.shared.u64 t, %1; cvt.u32.u64 %0, t; }" : "=r"(a) : "l"(p));
    return a;
}

#define CP16(dst, src) \
    asm volatile("cp.async.cg.shared.global [%0], [%1], 16;" :: "r"(dst), "l"(src) : "memory")
#define CP_COMMIT() asm volatile("cp.async.commit_group;" ::: "memory")
#define CP_WAIT0()  asm volatile("cp.async.wait_group 0;" ::: "memory")

__device__ __forceinline__ void ldm_x4(uint32_t* r, uint32_t addr) {
    asm volatile("ldmatrix.sync.aligned.m8n8.x4.shared.b16 {%0,%1,%2,%3}, [%4];"
                 : "=r"(r[0]), "=r"(r[1]), "=r"(r[2]), "=r"(r[3]) : "r"(addr));
}
__device__ __forceinline__ void ldm_x2(uint32_t* r, uint32_t addr) {
    asm volatile("ldmatrix.sync.aligned.m8n8.x2.shared.b16 {%0,%1}, [%2];"
                 : "=r"(r[0]), "=r"(r[1]) : "r"(addr));
}
__device__ __forceinline__ void mma16816(float* c, const uint32_t* a, const uint32_t* b) {
    asm volatile(
        "mma.sync.aligned.m16n8k16.row.col.f32.bf16.bf16.f32 "
        "{%0,%1,%2,%3}, {%4,%5,%6,%7}, {%8,%9}, {%0,%1,%2,%3};"
        : "+f"(c[0]), "+f"(c[1]), "+f"(c[2]), "+f"(c[3])
        : "r"(a[0]), "r"(a[1]), "r"(a[2]), "r"(a[3]), "r"(b[0]), "r"(b[1]));
}

// ---------------------------------------------------------------------------
// HMMA GEMM (bf16 two-term split): C = A * B^T
//   Ahi/Alo: [M][K] bf16; Bhi/Blo: [N][K] bf16. M%128==0, N%128==0, K%32==0.
//   Tile 128x128xBK32, 8 warps (2x4), warp tile 64x32, m16n8k16 atoms.
//   EPI 0: C[row*N+col] = v.  EPI 1: col<DM -> g_xs0, else silu -> g_sres.
// ---------------------------------------------------------------------------
#define HG_STRIDE 40               // bf16 elems per smem row (32 data + 8 pad)
#define HG_TILEB  (128*HG_STRIDE*2)   // 10240 bytes per tile
#define HG_STAGEB (4*HG_TILEB)        // 40960 bytes per stage
#define HG_SMEM   (2*HG_STAGEB)       // 81920 bytes

template<int EPI>
__global__ __launch_bounds__(256)
void hgemm(const __nv_bfloat16* __restrict__ Ahi, const __nv_bfloat16* __restrict__ Alo,
           const __nv_bfloat16* __restrict__ Bhi, const __nv_bfloat16* __restrict__ Blo,
           float* __restrict__ C, int N, int K) {
    extern __shared__ char hsm[];
    const uint32_t sb = smem_u32(hsm);
    const int tid = threadIdx.x;
    const int lane = tid & 31, wid = tid >> 5;
    const int wm = wid >> 2, wn = wid & 3;         // warp grid 2 (m) x 4 (n)
    const int bm = blockIdx.x * 128, bn = blockIdx.y * 128;

    float acc[4][4][4];
#pragma unroll
    for (int i = 0; i < 4; i++)
#pragma unroll
        for (int j = 0; j < 4; j++)
#pragma unroll
            for (int q = 0; q < 4; q++) acc[i][j][q] = 0.f;

    const int lr = tid >> 2;       // 0..63
    const int lc = (tid & 3) * 8;  // bf16 col offset: 0,8,16,24

    // issue cp.async for chunk c into stage s
    auto issue = [&](int c, int s) {
        const int k0 = c * 32;
        const uint32_t st = sb + s * HG_STAGEB;
#pragma unroll
        for (int h = 0; h < 2; h++) {
            const int row = lr + h * 64;
            const uint32_t so = (uint32_t)(row * HG_STRIDE + lc) * 2;
            const size_t ga = (size_t)(bm + row) * K + k0 + lc;
            const size_t gb = (size_t)(bn + row) * K + k0 + lc;
            CP16(st + 0 * HG_TILEB + so, Ahi + ga);
            CP16(st + 1 * HG_TILEB + so, Alo + ga);
            CP16(st + 2 * HG_TILEB + so, Bhi + gb);
            CP16(st + 3 * HG_TILEB + so, Blo + gb);
        }
    };

    const int nch = K / 32;
    issue(0, 0);
    CP_COMMIT();

    // ldmatrix lane addressing
    const int a_r = lane & 15;            // row within 16-row atom
    const int a_k = (lane >> 4) * 8;      // 0 or 8
    const int l16 = lane & 15;
    const int b_r = l16 & 7;
    const int b_k = (l16 >> 3) * 8;

    for (int c = 0; c < nch; c++) {
        CP_WAIT0();
        __syncthreads();
        if (c + 1 < nch) { issue(c + 1, (c + 1) & 1); CP_COMMIT(); }

        const uint32_t st = sb + (c & 1) * HG_STAGEB;
#pragma unroll
        for (int ks = 0; ks < 32; ks += 16) {
            uint32_t ah[4][4], al[4][4], bh[4][2], bl[4][2];
#pragma unroll
            for (int ma = 0; ma < 4; ma++) {
                const uint32_t off =
                    (uint32_t)((wm * 64 + ma * 16 + a_r) * HG_STRIDE + ks + a_k) * 2;
                ldm_x4(ah[ma], st + 0 * HG_TILEB + off);
                ldm_x4(al[ma], st + 1 * HG_TILEB + off);
            }
#pragma unroll
            for (int na = 0; na < 4; na++) {
                const uint32_t off =
                    (uint32_t)((wn * 32 + na * 8 + b_r) * HG_STRIDE + ks + b_k) * 2;
                ldm_x2(bh[na], st + 2 * HG_TILEB + off);
                ldm_x2(bl[na], st + 3 * HG_TILEB + off);
            }
#pragma unroll
            for (int ma = 0; ma < 4; ma++)
#pragma unroll
                for (int na = 0; na < 4; na++) {
                    mma16816(acc[ma][na], ah[ma], bh[na]);
                    mma16816(acc[ma][na], ah[ma], bl[na]);
                    mma16816(acc[ma][na], al[ma], bh[na]);
                }
        }
        __syncthreads();
    }

    // epilogue: direct stores (float2 pairs)
    const int eg = lane >> 2, ei = lane & 3;
#pragma unroll
    for (int ma = 0; ma < 4; ma++) {
#pragma unroll
        for (int na = 0; na < 4; na++) {
            const int row0 = bm + wm * 64 + ma * 16 + eg;
            const int col  = bn + wn * 32 + na * 8 + ei * 2;
#pragma unroll
            for (int h = 0; h < 2; h++) {
                const int row = row0 + h * 8;
                const float v0 = acc[ma][na][h * 2 + 0];
                const float v1 = acc[ma][na][h * 2 + 1];
                if (EPI == 0) {
                    *(float2*)(&C[(size_t)row * N + col]) = make_float2(v0, v1);
                } else {
                    if (col < DM) {
                        *(float2*)(&g_xs0[(size_t)row * DM + col]) = make_float2(v0, v1);
                    } else {
                        *(float2*)(&g_sres[(size_t)row * DM + (col - DM)]) =
                            make_float2(silu_f(v0), silu_f(v1));
                    }
                }
            }
        }
    }
}

// ---------------------------------------------------------------------------
// Prep kernels: fp32 -> bf16 hi/lo split (and transpose for weights)
// ---------------------------------------------------------------------------
__device__ __forceinline__ void split_bf16(float x, __nv_bfloat16& h, __nv_bfloat16& l) {
    h = __float2bfloat16(x);
    l = __float2bfloat16(x - __bfloat162float(h));
}

__global__ __launch_bounds__(256)
void prep_x_kernel(const float* __restrict__ x) {
    int i = blockIdx.x * blockDim.x + threadIdx.x;
    if (i >= ML * DM) return;
    split_bf16(x[i], g_xhi[i], g_xlo[i]);
}

// transpose W [K][N] -> hi/lo [N][K].  grid (K/32, N/32), block (32,8)
__global__ __launch_bounds__(256)
void prep_w_kernel(const float* __restrict__ W, __nv_bfloat16* __restrict__ Whi,
                   __nv_bfloat16* __restrict__ Wlo, int Kdim, int Ndim) {
    __shared__ float tl[32][33];
    const int k0 = blockIdx.x * 32, n0 = blockIdx.y * 32;
#pragma unroll
    for (int j = 0; j < 4; j++)
        tl[threadIdx.y + j * 8][threadIdx.x] =
            W[(size_t)(k0 + threadIdx.y + j * 8) * Ndim + n0 + threadIdx.x];
    __syncthreads();
#pragma unroll
    for (int j = 0; j < 4; j++) {
        int n = n0 + threadIdx.y + j * 8;
        int k = k0 + threadIdx.x;
        __nv_bfloat16 h, l;
        split_bf16(tl[threadIdx.x][threadIdx.y + j * 8], h, l);
        Whi[(size_t)n * Kdim + k] = h;
        Wlo[(size_t)n * Kdim + k] = l;
    }
}

// ---------------------------------------------------------------------------
// FFMA SGEMM (small GEMMs: N=80 split-K, delta K=48)
// ---------------------------------------------------------------------------
#define Bb_M 128
#define Bb_N 128
#define Bb_K 16

template<int EPI>
__global__ __launch_bounds__(256, 2)
void sgemm_pipe(const float* __restrict__ A, const float* __restrict__ B,
                const float* __restrict__ bias, float* __restrict__ C0,
                int M, int N, int K, int lda, int ldb, int kspl) {
    __shared__ float As[2][Bb_K][Bb_M + 4];
    __shared__ float Bs[2][Bb_K][Bb_N];
    const int tid = threadIdx.x;
    const int bm = blockIdx.x * Bb_M;
    const int bn = blockIdx.y * Bb_N;
    const int tx = tid & 15, ty = tid >> 4;

    const float* Ap = A; const float* Bp = B; float* Cp = C0;
    int kcnt = K;
    if (gridDim.z > 1) {
        kcnt = kspl;
        Ap += (size_t)blockIdx.z * kspl;
        Bp += (size_t)blockIdx.z * kspl * ldb;
        Cp += (size_t)blockIdx.z * M * N;
    }
    const int am0 = tid >> 2, ak = (tid & 3) * 4;
    const int bk0 = tid >> 5, bn0 = (tid & 31) * 4;
    const bool bok = (bn + bn0 + 3) < N;
    float4 ra0, ra1, rb0, rb1;
    float acc[8][8];
#pragma unroll
    for (int i = 0; i < 8; i++)
#pragma unroll
        for (int j = 0; j < 8; j++) acc[i][j] = 0.f;
    {
        ra0 = *(const float4*)(Ap + (size_t)(bm + am0) * lda + ak);
        ra1 = *(const float4*)(Ap + (size_t)(bm + am0 + 64) * lda + ak);
        rb0 = bok ? *(const float4*)(Bp + (size_t)bk0 * ldb + bn + bn0) : make_float4(0,0,0,0);
        rb1 = bok ? *(const float4*)(Bp + (size_t)(bk0 + 8) * ldb + bn + bn0) : make_float4(0,0,0,0);
        As[0][ak+0][am0] = ra0.x; As[0][ak+1][am0] = ra0.y; As[0][ak+2][am0] = ra0.z; As[0][ak+3][am0] = ra0.w;
        As[0][ak+0][am0+64] = ra1.x; As[0][ak+1][am0+64] = ra1.y; As[0][ak+2][am0+64] = ra1.z; As[0][ak+3][am0+64] = ra1.w;
        *(float4*)(&Bs[0][bk0][bn0]) = rb0;
        *(float4*)(&Bs[0][bk0+8][bn0]) = rb1;
    }
    __syncthreads();
    const int nt = kcnt / Bb_K;
    for (int t = 0; t < nt; t++) {
        const int cur = t & 1, k0n = (t + 1) * Bb_K;
        if (t + 1 < nt) {
            ra0 = *(const float4*)(Ap + (size_t)(bm + am0) * lda + k0n + ak);
            ra1 = *(const float4*)(Ap + (size_t)(bm + am0 + 64) * lda + k0n + ak);
            rb0 = bok ? *(const float4*)(Bp + (size_t)(k0n + bk0) * ldb + bn + bn0) : make_float4(0,0,0,0);
            rb1 = bok ? *(const float4*)(Bp + (size_t)(k0n + bk0 + 8) * ldb + bn + bn0) : make_float4(0,0,0,0);
        }
#pragma unroll
        for (int k = 0; k < Bb_K; k++) {
            float a[8], b[8];
            *(float4*)(a)     = *(const float4*)(&As[cur][k][ty * 8]);
            *(float4*)(a + 4) = *(const float4*)(&As[cur][k][ty * 8 + 4]);
            *(float4*)(b)     = *(const float4*)(&Bs[cur][k][tx * 8]);
            *(float4*)(b + 4) = *(const float4*)(&Bs[cur][k][tx * 8 + 4]);
#pragma unroll
            for (int i = 0; i < 8; i++)
#pragma unroll
                for (int j = 0; j < 8; j++)
                    acc[i][j] = fmaf(a[i], b[j], acc[i][j]);
        }
        if (t + 1 < nt) {
            const int nx = cur ^ 1;
            As[nx][ak+0][am0] = ra0.x; As[nx][ak+1][am0] = ra0.y; As[nx][ak+2][am0] = ra0.z; As[nx][ak+3][am0] = ra0.w;
            As[nx][ak+0][am0+64] = ra1.x; As[nx][ak+1][am0+64] = ra1.y; As[nx][ak+2][am0+64] = ra1.z; As[nx][ak+3][am0+64] = ra1.w;
            *(float4*)(&Bs[nx][bk0][bn0]) = rb0;
            *(float4*)(&Bs[nx][bk0+8][bn0]) = rb1;
        }
        __syncthreads();
    }
#pragma unroll
    for (int i = 0; i < 8; i++) {
        const int row = bm + ty * 8 + i;
#pragma unroll
        for (int jj = 0; jj < 8; jj += 4) {
            const int col = bn + tx * 8 + jj;
            if (col >= N) continue;
            if (EPI == 0) {
                *(float4*)(&Cp[(size_t)row * N + col]) =
                    make_float4(acc[i][jj], acc[i][jj+1], acc[i][jj+2], acc[i][jj+3]);
            } else {
                float o[4];
#pragma unroll
                for (int q = 0; q < 4; q++) {
                    float v = acc[i][jj+q] + bias[col+q];
                    float sp = (v > 0.f) ? (v + log1pf(__expf(-v))) : log1pf(__expf(v));
                    o[q] = fminf(fmaxf(sp, 1e-4f), 0.1f);
                }
                *(float4*)(&Cp[(size_t)row * N + col]) = make_float4(o[0], o[1], o[2], o[3]);
            }
        }
    }
}

__global__ __launch_bounds__(256)
void reduce_xp_kernel() {
    int idx = blockIdx.x * blockDim.x + threadIdx.x;
    float s = 0.f;
#pragma unroll
    for (int z = 0; z < 8; z++) s += g_xpp[(size_t)z * ML * XPW + idx];
    g_xp[idx] = s;
    int c = idx % XPW, r = idx / XPW;
    if (c >= DR) {
        int b = r / LL, t = r % LL;
        g_bcT[((size_t)b * 2 * NS + (c - DR)) * LL + t] = s;
    }
}

// ---------------------------------------------------------------------------
__global__ __launch_bounds__(256)
void conv_silu_kernel(const float* __restrict__ conv_w, const float* __restrict__ conv_b) {
    int idx = blockIdx.x * blockDim.x + threadIdx.x;
    if (idx >= ML * DM) return;
    int d = idx % DM;
    int t = (idx / DM) % LL;
    int base = idx - t * DM - d;
    float acc = conv_b[d];
#pragma unroll
    for (int k = 0; k < KC; k++) {
        int tt = t - (KC - 1) + k;
        if (tt >= 0)
            acc = fmaf(conv_w[d * KC + k], g_xs0[base + tt * DM + d], acc);
    }
    g_u[idx] = silu_f(acc);
}

__global__ __launch_bounds__(256)
void trans_fwd_kernel() {
    __shared__ float t0[32][33];
    __shared__ float t1[32][33];
    const int r0 = blockIdx.x * 32, d0 = blockIdx.y * 32;
    const int b = r0 / LL, tb = r0 % LL;
#pragma unroll
    for (int j = 0; j < 4; j++) {
        int row = r0 + threadIdx.y + j * 8;
        int d = d0 + threadIdx.x;
        float dl = g_delta[(size_t)row * DM + d];
        float uu = g_u[(size_t)row * DM + d];
        t0[threadIdx.y + j * 8][threadIdx.x] = dl;
        t1[threadIdx.y + j * 8][threadIdx.x] = dl * uu;
    }
    __syncthreads();
#pragma unroll
    for (int j = 0; j < 4; j++) {
        int d = d0 + threadIdx.y + j * 8;
        int t = tb + threadIdx.x;
        g_deltaT[((size_t)b * DM + d) * LL + t] = t0[threadIdx.x][threadIdx.y + j * 8];
        g_duT   [((size_t)b * DM + d) * LL + t] = t1[threadIdx.x][threadIdx.y + j * 8];
    }
}

__global__ __launch_bounds__(256)
void scan_par_kernel(const float* __restrict__ A_log) {
    __shared__ float pd[LL];
    __shared__ float du[LL];
    __shared__ float ysw[8][LL];
    __shared__ float wsum[9];
    const int bd = blockIdx.x;
    const int b = bd / DM, d = bd - b * DM;
    const int tid = threadIdx.x, lane = tid & 31, wrp = tid >> 5;
    const float* dT  = g_deltaT + (size_t)bd * LL;
    const float* duT = g_duT    + (size_t)bd * LL;

    float4 v = ((const float4*)dT)[tid];
    ((float4*)du)[tid] = ((const float4*)duT)[tid];
    float s0 = v.x, s1 = s0 + v.y, s2 = s1 + v.z, s3 = s2 + v.w;
    float ts = s3;
#pragma unroll
    for (int o = 1; o < 32; o <<= 1) {
        float nv = __shfl_up_sync(0xffffffffu, ts, o);
        if (lane >= o) ts += nv;
    }
    if (lane == 31) wsum[wrp] = ts;
#pragma unroll
    for (int k = 0; k < LL / 32 / 4; k++)
        ((float4*)ysw[wrp])[lane + k * 32] = make_float4(0.f, 0.f, 0.f, 0.f);
    __syncthreads();
    if (tid == 0) {
        float a = 0.f;
#pragma unroll
        for (int i = 0; i < 8; i++) { float x = wsum[i]; wsum[i] = a; a += x; }
        wsum[8] = a;
    }
    __syncthreads();
    float base = wsum[wrp] + ts - s3;
    pd[tid * 4 + 0] = base + s0;
    pd[tid * 4 + 1] = base + s1;
    pd[tid * 4 + 2] = base + s2;
    pd[tid * 4 + 3] = base + s3;
    const float S = wsum[8];
    __syncthreads();

#pragma unroll
    for (int sp = 0; sp < 2; sp++) {
        const int n = wrp + sp * 8;
        const float An = -__expf(A_log[d * NS + n]);
        const float* Bn = g_bcT + ((size_t)b * 2 * NS + n) * LL;
        const float* Cn = g_bcT + ((size_t)b * 2 * NS + NS + n) * LL;
        float carry = 0.f;
        for (int j = 0; j < 32; j++) {
            const int t = j * 32 + lane;
            float e = __expf(An * (S - pd[t]));
            float z = du[t] * Bn[t] * e;
            float sc = z;
#pragma unroll
            for (int o = 1; o < 32; o <<= 1) {
                float nv = __shfl_up_sync(0xffffffffu, sc, o);
                if (lane >= o) sc += nv;
            }
            float num = carry + sc;
            carry = __shfl_sync(0xffffffffu, num, 31);
            float x = num / (e + 1e-12f);
            ysw[wrp][t] += x * Cn[t];
        }
    }
    __syncthreads();
    float4 r = ((const float4*)ysw[0])[tid];
#pragma unroll
    for (int w = 1; w < 8; w++) {
        float4 q = ((const float4*)ysw[w])[tid];
        r.x += q.x; r.y += q.y; r.z += q.z; r.w += q.w;
    }
    ((float4*)(g_yT + (size_t)bd * LL))[tid] = r;
}

// transpose back + gate + bf16 split of y
__global__ __launch_bounds__(256)
void back_gate_kernel(const float* __restrict__ D_param) {
    __shared__ float tl[32][33];
    const int r0 = blockIdx.x * 32, d0 = blockIdx.y * 32;
    const int b = r0 / LL, tb = r0 % LL;
#pragma unroll
    for (int j = 0; j < 4; j++) {
        int d = d0 + threadIdx.y + j * 8;
        tl[threadIdx.y + j * 8][threadIdx.x] =
            g_yT[((size_t)b * DM + d) * LL + tb + threadIdx.x];
    }
    __syncthreads();
#pragma unroll
    for (int j = 0; j < 4; j++) {
        int row = r0 + threadIdx.y + j * 8;
        int d = d0 + threadIdx.x;
        float v = tl[threadIdx.x][threadIdx.y + j * 8];
        float uu = g_u[(size_t)row * DM + d];
        float sr = g_sres[(size_t)row * DM + d];
        float y = (v + uu * D_param[d]) * sr;
        __nv_bfloat16 h, l;
        split_bf16(y, h, l);
        g_yhi[(size_t)row * DM + d] = h;
        g_ylo[(size_t)row * DM + d] = l;
    }
}

// ---------------------------------------------------------------------------
extern "C" void kernel_launch(void* const* d_in, const int* in_sizes, int n_in,
                              void* d_out, int out_size) {
    const float* x       = (const float*)d_in[0];
    const float* W_in    = (const float*)d_in[1];
    const float* conv_w  = (const float*)d_in[2];
    const float* conv_b  = (const float*)d_in[3];
    const float* W_x     = (const float*)d_in[4];
    const float* W_delta = (const float*)d_in[5];
    const float* b_delta = (const float*)d_in[6];
    const float* A_log   = (const float*)d_in[7];
    const float* D_param = (const float*)d_in[8];
    const float* W_out   = (const float*)d_in[9];
    float* out = (float*)d_out;

    cudaFuncSetAttribute(hgemm<0>, cudaFuncAttributeMaxDynamicSharedMemorySize, HG_SMEM);
    cudaFuncSetAttribute(hgemm<1>, cudaFuncAttributeMaxDynamicSharedMemorySize, HG_SMEM);

    float *p_xp, *p_delta, *p_xpp, *p_u;
    cudaGetSymbolAddress((void**)&p_xp,    g_xp);
    cudaGetSymbolAddress((void**)&p_delta, g_delta);
    cudaGetSymbolAddress((void**)&p_xpp,   g_xpp);
    cudaGetSymbolAddress((void**)&p_u,     g_u);
    __nv_bfloat16 *p_xhi, *p_xlo, *p_yhi, *p_ylo, *p_wihi, *p_wilo, *p_wohi, *p_wolo;
    cudaGetSymbolAddress((void**)&p_xhi, g_xhi);
    cudaGetSymbolAddress((void**)&p_xlo, g_xlo);
    cudaGetSymbolAddress((void**)&p_yhi, g_yhi);
    cudaGetSymbolAddress((void**)&p_ylo, g_ylo);
    cudaGetSymbolAddress((void**)&p_wihi, g_wihi);
    cudaGetSymbolAddress((void**)&p_wilo, g_wilo);
    cudaGetSymbolAddress((void**)&p_wohi, g_wohi);
    cudaGetSymbolAddress((void**)&p_wolo, g_wolo);

    // prep: split x, transpose+split weights
    prep_x_kernel<<<(ML * DM + 255) / 256, 256>>>(x);
    prep_w_kernel<<<dim3(DM / 32, 2 * DM / 32), dim3(32, 8)>>>(W_in, p_wihi, p_wilo, DM, 2 * DM);
    prep_w_kernel<<<dim3(DM / 32, DM / 32), dim3(32, 8)>>>(W_out, p_wohi, p_wolo, DM, DM);

    // 1) gemm1 (HMMA): x @ W_in -> xs0 | silu(res)
    hgemm<1><<<dim3(ML / 128, (2 * DM) / 128), 256, HG_SMEM>>>(
        p_xhi, p_xlo, p_wihi, p_wilo, nullptr, 2 * DM, DM);
    // 2) conv + silu -> u
    conv_silu_kernel<<<(ML * DM + 255) / 256, 256>>>(conv_w, conv_b);
    // 3) gemm_x (FFMA split-K=8): u @ W_x
    {
        dim3 grid(ML / Bb_M, 1, 8);
        sgemm_pipe<0><<<grid, 256>>>(p_u, W_x, nullptr, p_xpp,
                                     ML, XPW, DM, DM, XPW, DM / 8);
    }
    reduce_xp_kernel<<<(ML * XPW) / 256, 256>>>();
    // 4) delta gemm
    {
        dim3 grid(ML / Bb_M, DM / Bb_N, 1);
        sgemm_pipe<2><<<grid, 256>>>(p_xp, W_delta, b_delta, p_delta,
                                     ML, DM, DR, XPW, DM, DR);
    }
    // 5) transpose, scan, gate(+split y)
    trans_fwd_kernel<<<dim3(ML / 32, DM / 32), dim3(32, 8)>>>();
    scan_par_kernel<<<BB * DM, 256>>>(A_log);
    back_gate_kernel<<<dim3(ML / 32, DM / 32), dim3(32, 8)>>>(D_param);
    // 6) gemm_out (HMMA): y @ W_out -> out
    hgemm<0><<<dim3(ML / 128, DM / 128), 256, HG_SMEM>>>(
        p_yhi, p_ylo, p_wohi, p_wolo, out, DM, DM);
}

// round 5
// speedup vs baseline: 4.8028x; 1.2894x over previous
#include <cuda_runtime.h>
#include <cuda_bf16.h>
#include <cstdint>
#include <math.h>

#define BB 2
#define LL 1024
#define DM 768
#define NS 16
#define KC 4
#define DR 48
#define ML (BB*LL)          // 2048 rows
#define XPW (DR + 2*NS)     // 80

// ---------------- scratch (device globals; allocation forbidden) ----------
__device__ float g_xs0[ML*DM];
__device__ float g_sres[ML*DM];
__device__ float g_u[ML*DM];
__device__ float g_delta[ML*DM];
__device__ float g_deltaT[ML*DM];     // (b,d,t)
__device__ float g_duT[ML*DM];        // (b,d,t) delta*u
__device__ float g_yT[ML*DM];         // (b,d,t) scan out
__device__ float g_bcT[BB*2*NS*LL];   // (b, ch, t): ch 0..15 = B, 16..31 = C

// bf16 hi/lo operands for HMMA GEMMs
__device__ __nv_bfloat16 g_xhi[ML*DM],  g_xlo[ML*DM];       // x split  [M][768]
__device__ __nv_bfloat16 g_uhi[ML*DM],  g_ulo[ML*DM];       // u split  [M][768]
__device__ __nv_bfloat16 g_yhi[ML*DM],  g_ylo[ML*DM];       // y split  [M][768]
__device__ __nv_bfloat16 g_xphi[ML*64], g_xplo[ML*64];      // xp[:, :48] split, K-pad 64 (cols 48..63 stay 0)
__device__ __nv_bfloat16 g_wihi[2*DM*DM], g_wilo[2*DM*DM];  // W_in^T  [1536][768]
__device__ __nv_bfloat16 g_wohi[DM*DM],   g_wolo[DM*DM];    // W_out^T [768][768]
__device__ __nv_bfloat16 g_wxhi[XPW*DM],  g_wxlo[XPW*DM];   // W_x^T   [80][768]
__device__ __nv_bfloat16 g_wdhi[DM*64],   g_wdlo[DM*64];    // W_delta^T [768][64] (cols 48..63 stay 0)

__device__ __forceinline__ float silu_f(float x) {
    return x / (1.0f + __expf(-x));
}
__device__ __forceinline__ uint32_t smem_u32(const void* p) {
    uint32_t a;
    asm("{ .reg .u64 t; cvta.to.shared.u64 t, %1; cvt.u32.u64 %0, t; }" : "=r"(a) : "l"(p));
    return a;
}
#define CP16(dst, src) \
    asm volatile("cp.async.cg.shared.global [%0], [%1], 16;" :: "r"(dst), "l"(src) : "memory")
#define CP_COMMIT() asm volatile("cp.async.commit_group;" ::: "memory")
#define CP_WAIT0()  asm volatile("cp.async.wait_group 0;" ::: "memory")

__device__ __forceinline__ void ldm_x4(uint32_t* r, uint32_t addr) {
    asm volatile("ldmatrix.sync.aligned.m8n8.x4.shared.b16 {%0,%1,%2,%3}, [%4];"
                 : "=r"(r[0]), "=r"(r[1]), "=r"(r[2]), "=r"(r[3]) : "r"(addr));
}
__device__ __forceinline__ void mma16816(float* c, const uint32_t* a, const uint32_t* b) {
    asm volatile(
        "mma.sync.aligned.m16n8k16.row.col.f32.bf16.bf16.f32 "
        "{%0,%1,%2,%3}, {%4,%5,%6,%7}, {%8,%9}, {%0,%1,%2,%3};"
        : "+f"(c[0]), "+f"(c[1]), "+f"(c[2]), "+f"(c[3])
        : "r"(a[0]), "r"(a[1]), "r"(a[2]), "r"(a[3]), "r"(b[0]), "r"(b[1]));
}
__device__ __forceinline__ void split_bf16(float x, __nv_bfloat16& h, __nv_bfloat16& l) {
    h = __float2bfloat16(x);
    l = __float2bfloat16(x - __bfloat162float(h));
}

// ---------------------------------------------------------------------------
// HMMA GEMM (bf16 two-term split, 3 product terms): C = A * B^T
//   A: [M][K] bf16 hi/lo, B: [N'][K] bf16 hi/lo with N' rows valid (guarded).
//   CTA tile 128x64xBK32, 8 warps (2x4), warp tile 64x16.
//   EPI 0: C[row*N+col] (plain, N=Nld)
//   EPI 1: gemm1: col<DM -> g_xs0, else silu -> g_sres
//   EPI 2: +bias, softplus, clip -> C[row*768+col]
//   EPI 3: gemm_x: col<48 -> split to g_xphi/g_xplo (stride 64);
//          48<=col<80 -> g_bcT[(b*32+col-48)*LL + t]
// ---------------------------------------------------------------------------
#define HG_STRIDE 40                   // bf16 per smem row (32 data + 8 pad)
#define HG_TA (128*HG_STRIDE*2)        // 10240 B
#define HG_TB (64*HG_STRIDE*2)         // 5120 B
#define HG_STAGE (2*HG_TA + 2*HG_TB)   // 30720 B
#define HG_SMEM (2*HG_STAGE)           // 61440 B

template<int EPI>
__global__ __launch_bounds__(256)
void hgemm(const __nv_bfloat16* __restrict__ Ahi, const __nv_bfloat16* __restrict__ Alo,
           const __nv_bfloat16* __restrict__ Bhi, const __nv_bfloat16* __restrict__ Blo,
           float* __restrict__ C, const float* __restrict__ bias, int N, int K) {
    extern __shared__ char hsm[];
    const uint32_t sb = smem_u32(hsm);
    const int tid = threadIdx.x;
    const int lane = tid & 31, wid = tid >> 5;
    const int wm = wid >> 2, wn = wid & 3;         // 2 (m) x 4 (n)
    const int bm = blockIdx.x * 128, bn = blockIdx.y * 64;

    float acc[4][2][4];
#pragma unroll
    for (int i = 0; i < 4; i++)
#pragma unroll
        for (int j = 0; j < 2; j++)
#pragma unroll
            for (int q = 0; q < 4; q++) acc[i][j][q] = 0.f;

    const int lr = tid >> 2;       // 0..63
    const int lc = (tid & 3) * 8;  // 0,8,16,24
    const bool bvalid = (bn + lr) < N;

    auto issue = [&](int c, int s) {
        const int k0 = c * 32;
        const uint32_t st = sb + s * HG_STAGE;
#pragma unroll
        for (int h = 0; h < 2; h++) {
            const int row = lr + h * 64;
            const uint32_t so = (uint32_t)(row * HG_STRIDE + lc) * 2;
            const size_t ga = (size_t)(bm + row) * K + k0 + lc;
            CP16(st + so, Ahi + ga);
            CP16(st + HG_TA + so, Alo + ga);
        }
        const uint32_t so = (uint32_t)(lr * HG_STRIDE + lc) * 2;
        if (bvalid) {
            const size_t gb = (size_t)(bn + lr) * K + k0 + lc;
            CP16(st + 2 * HG_TA + so, Bhi + gb);
            CP16(st + 2 * HG_TA + HG_TB + so, Blo + gb);
        } else {
            *(uint4*)(hsm + s * HG_STAGE + 2 * HG_TA + so) = make_uint4(0, 0, 0, 0);
            *(uint4*)(hsm + s * HG_STAGE + 2 * HG_TA + HG_TB + so) = make_uint4(0, 0, 0, 0);
        }
    };

    const int nch = K / 32;
    issue(0, 0);
    CP_COMMIT();

    const int a_r = lane & 15;
    const int a_k = (lane >> 4) * 8;
    const int b_row = ((lane >> 4) & 1) * 8 + (lane & 7);
    const int b_kk = ((lane >> 3) & 1) * 8;

    for (int c = 0; c < nch; c++) {
        CP_WAIT0();
        __syncthreads();
        if (c + 1 < nch) { issue(c + 1, (c + 1) & 1); CP_COMMIT(); }

        const uint32_t st = sb + (c & 1) * HG_STAGE;
#pragma unroll
        for (int ks = 0; ks < 32; ks += 16) {
            uint32_t ah[4][4], al[4][4], bh[4], bl[4];
#pragma unroll
            for (int ma = 0; ma < 4; ma++) {
                const uint32_t off =
                    (uint32_t)((wm * 64 + ma * 16 + a_r) * HG_STRIDE + ks + a_k) * 2;
                ldm_x4(ah[ma], st + off);
                ldm_x4(al[ma], st + HG_TA + off);
            }
            {
                const uint32_t off =
                    (uint32_t)((wn * 16 + b_row) * HG_STRIDE + ks + b_kk) * 2;
                ldm_x4(bh, st + 2 * HG_TA + off);
                ldm_x4(bl, st + 2 * HG_TA + HG_TB + off);
            }
#pragma unroll
            for (int ma = 0; ma < 4; ma++)
#pragma unroll
                for (int na = 0; na < 2; na++) {
                    mma16816(acc[ma][na], ah[ma], bh + na * 2);
                    mma16816(acc[ma][na], ah[ma], bl + na * 2);
                    mma16816(acc[ma][na], al[ma], bh + na * 2);
                }
        }
        // single sync per chunk: top-of-loop sync proves all warps done with the
        // stage that issue() will overwrite next iteration.
    }

    // epilogue
    const int eg = lane >> 2, ei = lane & 3;
#pragma unroll
    for (int ma = 0; ma < 4; ma++) {
#pragma unroll
        for (int na = 0; na < 2; na++) {
            const int col = bn + wn * 16 + na * 8 + ei * 2;
#pragma unroll
            for (int h = 0; h < 2; h++) {
                const int row = bm + wm * 64 + ma * 16 + eg + h * 8;
                const float v0 = acc[ma][na][h * 2 + 0];
                const float v1 = acc[ma][na][h * 2 + 1];
                if (EPI == 0) {
                    *(float2*)(&C[(size_t)row * N + col]) = make_float2(v0, v1);
                } else if (EPI == 1) {
                    if (col < DM)
                        *(float2*)(&g_xs0[(size_t)row * DM + col]) = make_float2(v0, v1);
                    else
                        *(float2*)(&g_sres[(size_t)row * DM + (col - DM)]) =
                            make_float2(silu_f(v0), silu_f(v1));
                } else if (EPI == 2) {
                    float o[2];
#pragma unroll
                    for (int q = 0; q < 2; q++) {
                        float v = (q ? v1 : v0) + bias[col + q];
                        float sp = (v > 0.f) ? (v + log1pf(__expf(-v))) : log1pf(__expf(v));
                        o[q] = fminf(fmaxf(sp, 1e-4f), 0.1f);
                    }
                    *(float2*)(&C[(size_t)row * DM + col]) = make_float2(o[0], o[1]);
                } else {   // EPI 3: gemm_x
#pragma unroll
                    for (int q = 0; q < 2; q++) {
                        const int cc = col + q;
                        if (cc >= XPW) continue;
                        const float v = q ? v1 : v0;
                        if (cc < DR) {
                            __nv_bfloat16 hh, ll;
                            split_bf16(v, hh, ll);
                            g_xphi[(size_t)row * 64 + cc] = hh;
                            g_xplo[(size_t)row * 64 + cc] = ll;
                        } else {
                            const int b = row / LL, t = row % LL;
                            g_bcT[((size_t)b * 2 * NS + (cc - DR)) * LL + t] = v;
                        }
                    }
                }
            }
        }
    }
}

// ---------------------------------------------------------------------------
// Prep kernels
// ---------------------------------------------------------------------------
__global__ __launch_bounds__(256)
void prep_x_kernel(const float* __restrict__ x) {
    int i = blockIdx.x * blockDim.x + threadIdx.x;
    if (i >= ML * DM) return;
    split_bf16(x[i], g_xhi[i], g_xlo[i]);
}

// transpose W [Kdim][Ndim] -> hi/lo [Ndim][ldout], guarded
__global__ __launch_bounds__(256)
void prep_w_kernel(const float* __restrict__ W, __nv_bfloat16* __restrict__ Whi,
                   __nv_bfloat16* __restrict__ Wlo, int Kdim, int Ndim, int ldout) {
    __shared__ float tl[32][33];
    const int k0 = blockIdx.x * 32, n0 = blockIdx.y * 32;
#pragma unroll
    for (int j = 0; j < 4; j++) {
        int k = k0 + threadIdx.y + j * 8;
        int n = n0 + threadIdx.x;
        tl[threadIdx.y + j * 8][threadIdx.x] =
            (k < Kdim && n < Ndim) ? W[(size_t)k * Ndim + n] : 0.f;
    }
    __syncthreads();
#pragma unroll
    for (int j = 0; j < 4; j++) {
        int n = n0 + threadIdx.y + j * 8;
        int k = k0 + threadIdx.x;
        if (n < Ndim && k < Kdim) {
            __nv_bfloat16 h, l;
            split_bf16(tl[threadIdx.x][threadIdx.y + j * 8], h, l);
            Whi[(size_t)n * ldout + k] = h;
            Wlo[(size_t)n * ldout + k] = l;
        }
    }
}

// ---------------------------------------------------------------------------
// Depthwise causal conv + bias + SiLU -> u (+ bf16 split for gemm_x)
// ---------------------------------------------------------------------------
__global__ __launch_bounds__(256)
void conv_silu_kernel(const float* __restrict__ conv_w, const float* __restrict__ conv_b) {
    int idx = blockIdx.x * blockDim.x + threadIdx.x;
    if (idx >= ML * DM) return;
    int d = idx % DM;
    int t = (idx / DM) % LL;
    int base = idx - t * DM - d;
    float acc = conv_b[d];
#pragma unroll
    for (int k = 0; k < KC; k++) {
        int tt = t - (KC - 1) + k;
        if (tt >= 0)
            acc = fmaf(conv_w[d * KC + k], g_xs0[base + tt * DM + d], acc);
    }
    float u = silu_f(acc);
    g_u[idx] = u;
    split_bf16(u, g_uhi[idx], g_ulo[idx]);
}

// ---------------------------------------------------------------------------
// Transpose fwd: delta, delta*u -> (b,d,t)
// ---------------------------------------------------------------------------
__global__ __launch_bounds__(256)
void trans_fwd_kernel() {
    __shared__ float t0[32][33];
    __shared__ float t1[32][33];
    const int r0 = blockIdx.x * 32, d0 = blockIdx.y * 32;
    const int b = r0 / LL, tb = r0 % LL;
#pragma unroll
    for (int j = 0; j < 4; j++) {
        int row = r0 + threadIdx.y + j * 8;
        int d = d0 + threadIdx.x;
        float dl = g_delta[(size_t)row * DM + d];
        float uu = g_u[(size_t)row * DM + d];
        t0[threadIdx.y + j * 8][threadIdx.x] = dl;
        t1[threadIdx.y + j * 8][threadIdx.x] = dl * uu;
    }
    __syncthreads();
#pragma unroll
    for (int j = 0; j < 4; j++) {
        int d = d0 + threadIdx.y + j * 8;
        int t = tb + threadIdx.x;
        g_deltaT[((size_t)b * DM + d) * LL + t] = t0[threadIdx.x][threadIdx.y + j * 8];
        g_duT   [((size_t)b * DM + d) * LL + t] = t1[threadIdx.x][threadIdx.y + j * 8];
    }
}

// ---------------------------------------------------------------------------
// Parallel selective scan. One block per (b,d). 8 warps; warp w owns states
// w and w+8, processes chunks of 128 t (4 per lane), interleaved chains.
// ---------------------------------------------------------------------------
__global__ __launch_bounds__(256)
void scan_par_kernel(const float* __restrict__ A_log) {
    __shared__ float pd[LL];
    __shared__ float du[LL];
    __shared__ float ysw[8][LL];
    __shared__ float wsum[9];
    const int bd = blockIdx.x;
    const int b = bd / DM, d = bd - b * DM;
    const int tid = threadIdx.x, lane = tid & 31, wrp = tid >> 5;
    const float* dT  = g_deltaT + (size_t)bd * LL;
    const float* duT = g_duT    + (size_t)bd * LL;

    // phase 1: block prefix-sum of delta
    float4 v = ((const float4*)dT)[tid];
    ((float4*)du)[tid] = ((const float4*)duT)[tid];
    float s0 = v.x, s1 = s0 + v.y, s2 = s1 + v.z, s3 = s2 + v.w;
    float ts = s3;
#pragma unroll
    for (int o = 1; o < 32; o <<= 1) {
        float nv = __shfl_up_sync(0xffffffffu, ts, o);
        if (lane >= o) ts += nv;
    }
    if (lane == 31) wsum[wrp] = ts;
#pragma unroll
    for (int k = 0; k < LL / 32 / 4; k++)
        ((float4*)ysw[wrp])[lane + k * 32] = make_float4(0.f, 0.f, 0.f, 0.f);
    __syncthreads();
    if (tid == 0) {
        float a = 0.f;
#pragma unroll
        for (int i = 0; i < 8; i++) { float x = wsum[i]; wsum[i] = a; a += x; }
        wsum[8] = a;
    }
    __syncthreads();
    float base = wsum[wrp] + ts - s3;
    pd[tid * 4 + 0] = base + s0;
    pd[tid * 4 + 1] = base + s1;
    pd[tid * 4 + 2] = base + s2;
    pd[tid * 4 + 3] = base + s3;
    const float S = wsum[8];
    __syncthreads();

    // phase 2: two interleaved states per warp
    const int n0 = wrp, n1 = wrp + 8;
    const float An0 = -__expf(A_log[d * NS + n0]);
    const float An1 = -__expf(A_log[d * NS + n1]);
    const float* B0p = g_bcT + ((size_t)b * 2 * NS + n0) * LL;
    const float* C0p = g_bcT + ((size_t)b * 2 * NS + NS + n0) * LL;
    const float* B1p = g_bcT + ((size_t)b * 2 * NS + n1) * LL;
    const float* C1p = g_bcT + ((size_t)b * 2 * NS + NS + n1) * LL;
    float carry0 = 0.f, carry1 = 0.f;

#pragma unroll
    for (int j = 0; j < 8; j++) {
        const int t = j * 128 + lane * 4;
        float dv[4], pv[4], b0[4], c0[4], b1[4], c1[4];
        *(float4*)dv = *(const float4*)&du[t];
        *(float4*)pv = *(const float4*)&pd[t];
        *(float4*)b0 = *(const float4*)&B0p[t];
        *(float4*)c0 = *(const float4*)&C0p[t];
        *(float4*)b1 = *(const float4*)&B1p[t];
        *(float4*)c1 = *(const float4*)&C1p[t];

        float e0[4], e1[4], p0[4], p1[4];
#pragma unroll
        for (int q = 0; q < 4; q++) {
            e0[q] = __expf(An0 * (S - pv[q]));
            e1[q] = __expf(An1 * (S - pv[q]));
            float z0 = dv[q] * b0[q] * e0[q];
            float z1 = dv[q] * b1[q] * e1[q];
            p0[q] = q ? (p0[q - 1] + z0) : z0;
            p1[q] = q ? (p1[q - 1] + z1) : z1;
        }
        float t0 = p0[3], t1 = p1[3];
#pragma unroll
        for (int o = 1; o < 32; o <<= 1) {
            float a0 = __shfl_up_sync(0xffffffffu, t0, o);
            float a1 = __shfl_up_sync(0xffffffffu, t1, o);
            if (lane >= o) { t0 += a0; t1 += a1; }
        }
        const float bs0 = carry0 + t0 - p0[3];
        const float bs1 = carry1 + t1 - p1[3];
        carry0 += __shfl_sync(0xffffffffu, t0, 31);
        carry1 += __shfl_sync(0xffffffffu, t1, 31);

        float acc4[4];
        *(float4*)acc4 = *(const float4*)&ysw[wrp][t];
#pragma unroll
        for (int q = 0; q < 4; q++) {
            float x0 = (bs0 + p0[q]) / (e0[q] + 1e-12f);
            float x1 = (bs1 + p1[q]) / (e1[q] + 1e-12f);
            acc4[q] += x0 * c0[q] + x1 * c1[q];
        }
        *(float4*)&ysw[wrp][t] = *(const float4*)acc4;
    }
    __syncthreads();

    // phase 3: reduce 8 warp rows
    float4 r = ((const float4*)ysw[0])[tid];
#pragma unroll
    for (int w = 1; w < 8; w++) {
        float4 q = ((const float4*)ysw[w])[tid];
        r.x += q.x; r.y += q.y; r.z += q.z; r.w += q.w;
    }
    ((float4*)(g_yT + (size_t)bd * LL))[tid] = r;
}

// ---------------------------------------------------------------------------
// Transpose back + gate + bf16 split of y
// ---------------------------------------------------------------------------
__global__ __launch_bounds__(256)
void back_gate_kernel(const float* __restrict__ D_param) {
    __shared__ float tl[32][33];
    const int r0 = blockIdx.x * 32, d0 = blockIdx.y * 32;
    const int b = r0 / LL, tb = r0 % LL;
#pragma unroll
    for (int j = 0; j < 4; j++) {
        int d = d0 + threadIdx.y + j * 8;
        tl[threadIdx.y + j * 8][threadIdx.x] =
            g_yT[((size_t)b * DM + d) * LL + tb + threadIdx.x];
    }
    __syncthreads();
#pragma unroll
    for (int j = 0; j < 4; j++) {
        int row = r0 + threadIdx.y + j * 8;
        int d = d0 + threadIdx.x;
        float v = tl[threadIdx.x][threadIdx.y + j * 8];
        float uu = g_u[(size_t)row * DM + d];
        float sr = g_sres[(size_t)row * DM + d];
        float y = (v + uu * D_param[d]) * sr;
        __nv_bfloat16 h, l;
        split_bf16(y, h, l);
        g_yhi[(size_t)row * DM + d] = h;
        g_ylo[(size_t)row * DM + d] = l;
    }
}

// ---------------------------------------------------------------------------
extern "C" void kernel_launch(void* const* d_in, const int* in_sizes, int n_in,
                              void* d_out, int out_size) {
    const float* x       = (const float*)d_in[0];
    const float* W_in    = (const float*)d_in[1];
    const float* conv_w  = (const float*)d_in[2];
    const float* conv_b  = (const float*)d_in[3];
    const float* W_x     = (const float*)d_in[4];
    const float* W_delta = (const float*)d_in[5];
    const float* b_delta = (const float*)d_in[6];
    const float* A_log   = (const float*)d_in[7];
    const float* D_param = (const float*)d_in[8];
    const float* W_out   = (const float*)d_in[9];
    float* out = (float*)d_out;

    cudaFuncSetAttribute(hgemm<0>, cudaFuncAttributeMaxDynamicSharedMemorySize, HG_SMEM);
    cudaFuncSetAttribute(hgemm<1>, cudaFuncAttributeMaxDynamicSharedMemorySize, HG_SMEM);
    cudaFuncSetAttribute(hgemm<2>, cudaFuncAttributeMaxDynamicSharedMemorySize, HG_SMEM);
    cudaFuncSetAttribute(hgemm<3>, cudaFuncAttributeMaxDynamicSharedMemorySize, HG_SMEM);

    float* p_delta;
    cudaGetSymbolAddress((void**)&p_delta, g_delta);
    __nv_bfloat16 *p_xhi, *p_xlo, *p_uhi, *p_ulo, *p_yhi, *p_ylo, *p_xphi, *p_xplo;
    __nv_bfloat16 *p_wihi, *p_wilo, *p_wohi, *p_wolo, *p_wxhi, *p_wxlo, *p_wdhi, *p_wdlo;
    cudaGetSymbolAddress((void**)&p_xhi, g_xhi);
    cudaGetSymbolAddress((void**)&p_xlo, g_xlo);
    cudaGetSymbolAddress((void**)&p_uhi, g_uhi);
    cudaGetSymbolAddress((void**)&p_ulo, g_ulo);
    cudaGetSymbolAddress((void**)&p_yhi, g_yhi);
    cudaGetSymbolAddress((void**)&p_ylo, g_ylo);
    cudaGetSymbolAddress((void**)&p_xphi, g_xphi);
    cudaGetSymbolAddress((void**)&p_xplo, g_xplo);
    cudaGetSymbolAddress((void**)&p_wihi, g_wihi);
    cudaGetSymbolAddress((void**)&p_wilo, g_wilo);
    cudaGetSymbolAddress((void**)&p_wohi, g_wohi);
    cudaGetSymbolAddress((void**)&p_wolo, g_wolo);
    cudaGetSymbolAddress((void**)&p_wxhi, g_wxhi);
    cudaGetSymbolAddress((void**)&p_wxlo, g_wxlo);
    cudaGetSymbolAddress((void**)&p_wdhi, g_wdhi);
    cudaGetSymbolAddress((void**)&p_wdlo, g_wdlo);

    // prep: split x; transpose+split all weights
    prep_x_kernel<<<(ML * DM + 255) / 256, 256>>>(x);
    prep_w_kernel<<<dim3(DM / 32, 2 * DM / 32), dim3(32, 8)>>>(W_in, p_wihi, p_wilo, DM, 2 * DM, DM);
    prep_w_kernel<<<dim3(DM / 32, DM / 32), dim3(32, 8)>>>(W_out, p_wohi, p_wolo, DM, DM, DM);
    prep_w_kernel<<<dim3(DM / 32, (XPW + 31) / 32), dim3(32, 8)>>>(W_x, p_wxhi, p_wxlo, DM, XPW, DM);
    prep_w_kernel<<<dim3((DR + 31) / 32, DM / 32), dim3(32, 8)>>>(W_delta, p_wdhi, p_wdlo, DR, DM, 64);

    // 1) gemm1: x @ W_in -> xs0 | silu(res)
    hgemm<1><<<dim3(ML / 128, (2 * DM) / 64), 256, HG_SMEM>>>(
        p_xhi, p_xlo, p_wihi, p_wilo, nullptr, nullptr, 2 * DM, DM);
    // 2) conv + silu -> u (+ split)
    conv_silu_kernel<<<(ML * DM + 255) / 256, 256>>>(conv_w, conv_b);
    // 3) gemm_x: u @ W_x -> xphi/xplo + bcT
    hgemm<3><<<dim3(ML / 128, 2), 256, HG_SMEM>>>(
        p_uhi, p_ulo, p_wxhi, p_wxlo, nullptr, nullptr, XPW, DM);
    // 4) delta: xp48 @ W_delta (+bias, softplus, clip)
    hgemm<2><<<dim3(ML / 128, DM / 64), 256, HG_SMEM>>>(
        p_xphi, p_xplo, p_wdhi, p_wdlo, p_delta, b_delta, DM, 64);
    // 5) transpose, scan, gate
    trans_fwd_kernel<<<dim3(ML / 32, DM / 32), dim3(32, 8)>>>();
    scan_par_kernel<<<BB * DM, 256>>>(A_log);
    back_gate_kernel<<<dim3(ML / 32, DM / 32), dim3(32, 8)>>>(D_param);
    // 6) out = y @ W_out
    hgemm<0><<<dim3(ML / 128, DM / 64), 256, HG_SMEM>>>(
        p_yhi, p_ylo, p_wohi, p_wolo, out, nullptr, DM, DM);
}

// round 6
// speedup vs baseline: 5.0289x; 1.0471x over previous
#include <cuda_runtime.h>
#include <cuda_bf16.h>
#include <cstdint>
#include <math.h>

#define BB 2
#define LL 1024
#define DM 768
#define NS 16
#define KC 4
#define DR 48
#define ML (BB*LL)          // 2048 rows
#define XPW (DR + 2*NS)     // 80

// ---------------- scratch (device globals; allocation forbidden) ----------
__device__ float g_xs0[ML*DM];
__device__ float g_sres[ML*DM];
__device__ float g_u[ML*DM];
__device__ float g_delta[ML*DM];
__device__ float g_deltaT[ML*DM];     // (b,d,t)
__device__ float g_duT[ML*DM];        // (b,d,t) delta*u
__device__ float g_yT[ML*DM];         // (b,d,t) scan out
__device__ float g_bcT[BB*2*NS*LL];   // (b, ch, t): ch 0..15 = B, 16..31 = C

// bf16 hi/lo operands for HMMA GEMMs
__device__ __nv_bfloat16 g_xhi[ML*DM],  g_xlo[ML*DM];       // x split  [M][768]
__device__ __nv_bfloat16 g_uhi[ML*DM],  g_ulo[ML*DM];       // u split  [M][768]
__device__ __nv_bfloat16 g_yhi[ML*DM],  g_ylo[ML*DM];       // y split  [M][768]
__device__ __nv_bfloat16 g_xphi[ML*64], g_xplo[ML*64];      // xp[:, :48] split (cols 48..63 stay 0)
__device__ __nv_bfloat16 g_wihi[2*DM*DM], g_wilo[2*DM*DM];  // W_in^T  [1536][768]
__device__ __nv_bfloat16 g_wohi[DM*DM],   g_wolo[DM*DM];    // W_out^T [768][768]
__device__ __nv_bfloat16 g_wxhi[XPW*DM],  g_wxlo[XPW*DM];   // W_x^T   [80][768]
__device__ __nv_bfloat16 g_wdhi[DM*64],   g_wdlo[DM*64];    // W_delta^T [768][64] (cols 48..63 stay 0)

__device__ __forceinline__ float silu_f(float x) {
    return x / (1.0f + __expf(-x));
}
__device__ __forceinline__ uint32_t smem_u32(const void* p) {
    uint32_t a;
    asm("{ .reg .u64 t; cvta.to.shared.u64 t, %1; cvt.u32.u64 %0, t; }" : "=r"(a) : "l"(p));
    return a;
}
#define CP16(dst, src) \
    asm volatile("cp.async.cg.shared.global [%0], [%1], 16;" :: "r"(dst), "l"(src) : "memory")
#define CP_COMMIT() asm volatile("cp.async.commit_group;" ::: "memory")
#define CP_WAIT1()  asm volatile("cp.async.wait_group 1;" ::: "memory")
#define CP_WAIT0()  asm volatile("cp.async.wait_group 0;" ::: "memory")

__device__ __forceinline__ void ldm_x4(uint32_t* r, uint32_t addr) {
    asm volatile("ldmatrix.sync.aligned.m8n8.x4.shared.b16 {%0,%1,%2,%3}, [%4];"
                 : "=r"(r[0]), "=r"(r[1]), "=r"(r[2]), "=r"(r[3]) : "r"(addr));
}
__device__ __forceinline__ void mma16816(float* c, const uint32_t* a, const uint32_t* b) {
    asm volatile(
        "mma.sync.aligned.m16n8k16.row.col.f32.bf16.bf16.f32 "
        "{%0,%1,%2,%3}, {%4,%5,%6,%7}, {%8,%9}, {%0,%1,%2,%3};"
        : "+f"(c[0]), "+f"(c[1]), "+f"(c[2]), "+f"(c[3])
        : "r"(a[0]), "r"(a[1]), "r"(a[2]), "r"(a[3]), "r"(b[0]), "r"(b[1]));
}
__device__ __forceinline__ void split_bf16(float x, __nv_bfloat16& h, __nv_bfloat16& l) {
    h = __float2bfloat16(x);
    l = __float2bfloat16(x - __bfloat162float(h));
}

// ---------------------------------------------------------------------------
// HMMA GEMM (bf16 two-term split, 3 product terms): C = A * B^T
//   CTA tile 128x64xBK32, 8 warps (2x4), 3-stage cp.async pipeline.
//   EPI 0: plain store. EPI 1: gemm1 split. EPI 2: softplus/clip. EPI 3: gemm_x.
// ---------------------------------------------------------------------------
#define HG_STRIDE 40                   // bf16 per smem row (32 data + 8 pad)
#define HG_TA (128*HG_STRIDE*2)        // 10240 B
#define HG_TB (64*HG_STRIDE*2)         // 5120 B
#define HG_STAGE (2*HG_TA + 2*HG_TB)   // 30720 B
#define HG_NSTG 3
#define HG_SMEM (HG_NSTG*HG_STAGE)     // 92160 B

template<int EPI>
__global__ __launch_bounds__(256, 2)
void hgemm(const __nv_bfloat16* __restrict__ Ahi, const __nv_bfloat16* __restrict__ Alo,
           const __nv_bfloat16* __restrict__ Bhi, const __nv_bfloat16* __restrict__ Blo,
           float* __restrict__ C, const float* __restrict__ bias, int N, int K) {
    extern __shared__ char hsm[];
    const uint32_t sb = smem_u32(hsm);
    const int tid = threadIdx.x;
    const int lane = tid & 31, wid = tid >> 5;
    const int wm = wid >> 2, wn = wid & 3;         // 2 (m) x 4 (n)
    const int bm = blockIdx.x * 128, bn = blockIdx.y * 64;

    float acc[4][2][4];
#pragma unroll
    for (int i = 0; i < 4; i++)
#pragma unroll
        for (int j = 0; j < 2; j++)
#pragma unroll
            for (int q = 0; q < 4; q++) acc[i][j][q] = 0.f;

    const int lr = tid >> 2;       // 0..63
    const int lc = (tid & 3) * 8;  // 0,8,16,24
    const bool bvalid = (bn + lr) < N;

    auto issue = [&](int c, int s) {
        const int k0 = c * 32;
        const uint32_t st = sb + s * HG_STAGE;
#pragma unroll
        for (int h = 0; h < 2; h++) {
            const int row = lr + h * 64;
            const uint32_t so = (uint32_t)(row * HG_STRIDE + lc) * 2;
            const size_t ga = (size_t)(bm + row) * K + k0 + lc;
            CP16(st + so, Ahi + ga);
            CP16(st + HG_TA + so, Alo + ga);
        }
        const uint32_t so = (uint32_t)(lr * HG_STRIDE + lc) * 2;
        if (bvalid) {
            const size_t gb = (size_t)(bn + lr) * K + k0 + lc;
            CP16(st + 2 * HG_TA + so, Bhi + gb);
            CP16(st + 2 * HG_TA + HG_TB + so, Blo + gb);
        } else {
            *(uint4*)(hsm + s * HG_STAGE + 2 * HG_TA + so) = make_uint4(0, 0, 0, 0);
            *(uint4*)(hsm + s * HG_STAGE + 2 * HG_TA + HG_TB + so) = make_uint4(0, 0, 0, 0);
        }
    };

    const int nch = K / 32;
    issue(0, 0);
    CP_COMMIT();
    if (nch > 1) { issue(1, 1); }
    CP_COMMIT();          // commit even if empty to keep group counting uniform

    const int a_r = lane & 15;
    const int a_k = (lane >> 4) * 8;
    const int b_row = ((lane >> 4) & 1) * 8 + (lane & 7);
    const int b_kk = ((lane >> 3) & 1) * 8;

    for (int c = 0; c < nch; c++) {
        CP_WAIT1();            // chunk c resident (c+1 may still be in flight)
        __syncthreads();       // also proves compute on stage (c-1)%3 finished
        if (c + 2 < nch) issue(c + 2, (c + 2) % HG_NSTG);
        CP_COMMIT();

        const uint32_t st = sb + (c % HG_NSTG) * HG_STAGE;
#pragma unroll
        for (int ks = 0; ks < 32; ks += 16) {
            uint32_t ah[4][4], al[4][4], bh[4], bl[4];
#pragma unroll
            for (int ma = 0; ma < 4; ma++) {
                const uint32_t off =
                    (uint32_t)((wm * 64 + ma * 16 + a_r) * HG_STRIDE + ks + a_k) * 2;
                ldm_x4(ah[ma], st + off);
                ldm_x4(al[ma], st + HG_TA + off);
            }
            {
                const uint32_t off =
                    (uint32_t)((wn * 16 + b_row) * HG_STRIDE + ks + b_kk) * 2;
                ldm_x4(bh, st + 2 * HG_TA + off);
                ldm_x4(bl, st + 2 * HG_TA + HG_TB + off);
            }
#pragma unroll
            for (int ma = 0; ma < 4; ma++)
#pragma unroll
                for (int na = 0; na < 2; na++) {
                    mma16816(acc[ma][na], ah[ma], bh + na * 2);
                    mma16816(acc[ma][na], ah[ma], bl + na * 2);
                    mma16816(acc[ma][na], al[ma], bh + na * 2);
                }
        }
    }

    // epilogue
    const int eg = lane >> 2, ei = lane & 3;
#pragma unroll
    for (int ma = 0; ma < 4; ma++) {
#pragma unroll
        for (int na = 0; na < 2; na++) {
            const int col = bn + wn * 16 + na * 8 + ei * 2;
#pragma unroll
            for (int h = 0; h < 2; h++) {
                const int row = bm + wm * 64 + ma * 16 + eg + h * 8;
                const float v0 = acc[ma][na][h * 2 + 0];
                const float v1 = acc[ma][na][h * 2 + 1];
                if (EPI == 0) {
                    *(float2*)(&C[(size_t)row * N + col]) = make_float2(v0, v1);
                } else if (EPI == 1) {
                    if (col < DM)
                        *(float2*)(&g_xs0[(size_t)row * DM + col]) = make_float2(v0, v1);
                    else
                        *(float2*)(&g_sres[(size_t)row * DM + (col - DM)]) =
                            make_float2(silu_f(v0), silu_f(v1));
                } else if (EPI == 2) {
                    float o[2];
#pragma unroll
                    for (int q = 0; q < 2; q++) {
                        float v = (q ? v1 : v0) + bias[col + q];
                        float sp = (v > 0.f) ? (v + log1pf(__expf(-v))) : log1pf(__expf(v));
                        o[q] = fminf(fmaxf(sp, 1e-4f), 0.1f);
                    }
                    *(float2*)(&C[(size_t)row * DM + col]) = make_float2(o[0], o[1]);
                } else {   // EPI 3: gemm_x
#pragma unroll
                    for (int q = 0; q < 2; q++) {
                        const int cc = col + q;
                        if (cc >= XPW) continue;
                        const float v = q ? v1 : v0;
                        if (cc < DR) {
                            __nv_bfloat16 hh, ll;
                            split_bf16(v, hh, ll);
                            g_xphi[(size_t)row * 64 + cc] = hh;
                            g_xplo[(size_t)row * 64 + cc] = ll;
                        } else {
                            const int b = row / LL, t = row % LL;
                            g_bcT[((size_t)b * 2 * NS + (cc - DR)) * LL + t] = v;
                        }
                    }
                }
            }
        }
    }
}

// ---------------------------------------------------------------------------
// Fused prep: x split (vectorized) + all 4 weight transposes in one launch.
// Block ranges: [0,1536) x-split; then W_in 1152; W_out 576; W_x 72; W_delta 48.
// ---------------------------------------------------------------------------
__device__ __forceinline__ void wtrans_tile(const float* __restrict__ W,
                                            __nv_bfloat16* __restrict__ Whi,
                                            __nv_bfloat16* __restrict__ Wlo,
                                            int Kdim, int Ndim, int ldout,
                                            int kb, int nb) {
    __shared__ float tl[32][33];
    const int k0 = kb * 32, n0 = nb * 32;
    const int tx = threadIdx.x & 31, ty = threadIdx.x >> 5;   // 32 x 8
#pragma unroll
    for (int j = 0; j < 4; j++) {
        int k = k0 + ty + j * 8;
        int n = n0 + tx;
        tl[ty + j * 8][tx] = (k < Kdim && n < Ndim) ? W[(size_t)k * Ndim + n] : 0.f;
    }
    __syncthreads();
#pragma unroll
    for (int j = 0; j < 4; j++) {
        int n = n0 + ty + j * 8;
        int k = k0 + tx;
        if (n < Ndim && k < Kdim) {
            __nv_bfloat16 h, l;
            split_bf16(tl[tx][ty + j * 8], h, l);
            Whi[(size_t)n * ldout + k] = h;
            Wlo[(size_t)n * ldout + k] = l;
        }
    }
}

#define PREP_XBLK (ML*DM/1024)     // 1536 (256 thr x 4 elems)
__global__ __launch_bounds__(256)
void prep_all_kernel(const float* __restrict__ x, const float* __restrict__ W_in,
                     const float* __restrict__ W_out, const float* __restrict__ W_x,
                     const float* __restrict__ W_delta) {
    int blk = blockIdx.x;
    if (blk < PREP_XBLK) {
        const int i4 = blk * 256 + threadIdx.x;     // float4 index
        float4 v = ((const float4*)x)[i4];
        __nv_bfloat16 h0, l0, h1, l1, h2, l2, h3, l3;
        split_bf16(v.x, h0, l0); split_bf16(v.y, h1, l1);
        split_bf16(v.z, h2, l2); split_bf16(v.w, h3, l3);
        __nv_bfloat162* ph = (__nv_bfloat162*)g_xhi;
        __nv_bfloat162* pl = (__nv_bfloat162*)g_xlo;
        ph[i4 * 2]     = __nv_bfloat162(h0, h1);
        ph[i4 * 2 + 1] = __nv_bfloat162(h2, h3);
        pl[i4 * 2]     = __nv_bfloat162(l0, l1);
        pl[i4 * 2 + 1] = __nv_bfloat162(l2, l3);
        return;
    }
    blk -= PREP_XBLK;
    if (blk < 1152) {       // W_in: K=768 (24 kb), N=1536 (48 nb)
        wtrans_tile(W_in, g_wihi, g_wilo, DM, 2 * DM, DM, blk % 24, blk / 24);
        return;
    }
    blk -= 1152;
    if (blk < 576) {        // W_out: 24 x 24
        wtrans_tile(W_out, g_wohi, g_wolo, DM, DM, DM, blk % 24, blk / 24);
        return;
    }
    blk -= 576;
    if (blk < 72) {         // W_x: K=768 (24), N=80 (3)
        wtrans_tile(W_x, g_wxhi, g_wxlo, DM, XPW, DM, blk % 24, blk / 24);
        return;
    }
    blk -= 72;
    // W_delta: K=48 (2), N=768 (24), ldout 64
    wtrans_tile(W_delta, g_wdhi, g_wdlo, DR, DM, 64, blk % 2, blk / 2);
}
#define PREP_BLKS (PREP_XBLK + 1152 + 576 + 72 + 48)

// ---------------------------------------------------------------------------
// Depthwise causal conv + bias + SiLU -> u (+ bf16 split for gemm_x)
// ---------------------------------------------------------------------------
__global__ __launch_bounds__(256)
void conv_silu_kernel(const float* __restrict__ conv_w, const float* __restrict__ conv_b) {
    int idx = blockIdx.x * blockDim.x + threadIdx.x;
    if (idx >= ML * DM) return;
    int d = idx % DM;
    int t = (idx / DM) % LL;
    int base = idx - t * DM - d;
    float acc = conv_b[d];
#pragma unroll
    for (int k = 0; k < KC; k++) {
        int tt = t - (KC - 1) + k;
        if (tt >= 0)
            acc = fmaf(conv_w[d * KC + k], g_xs0[base + tt * DM + d], acc);
    }
    float u = silu_f(acc);
    g_u[idx] = u;
    split_bf16(u, g_uhi[idx], g_ulo[idx]);
}

// ---------------------------------------------------------------------------
// Transpose fwd: delta, delta*u -> (b,d,t)
// ---------------------------------------------------------------------------
__global__ __launch_bounds__(256)
void trans_fwd_kernel() {
    __shared__ float t0[32][33];
    __shared__ float t1[32][33];
    const int r0 = blockIdx.x * 32, d0 = blockIdx.y * 32;
    const int b = r0 / LL, tb = r0 % LL;
#pragma unroll
    for (int j = 0; j < 4; j++) {
        int row = r0 + threadIdx.y + j * 8;
        int d = d0 + threadIdx.x;
        float dl = g_delta[(size_t)row * DM + d];
        float uu = g_u[(size_t)row * DM + d];
        t0[threadIdx.y + j * 8][threadIdx.x] = dl;
        t1[threadIdx.y + j * 8][threadIdx.x] = dl * uu;
    }
    __syncthreads();
#pragma unroll
    for (int j = 0; j < 4; j++) {
        int d = d0 + threadIdx.y + j * 8;
        int t = tb + threadIdx.x;
        g_deltaT[((size_t)b * DM + d) * LL + t] = t0[threadIdx.x][threadIdx.y + j * 8];
        g_duT   [((size_t)b * DM + d) * LL + t] = t1[threadIdx.x][threadIdx.y + j * 8];
    }
}

// ---------------------------------------------------------------------------
// Parallel selective scan. One block per (b,d).
// ---------------------------------------------------------------------------
__global__ __launch_bounds__(256)
void scan_par_kernel(const float* __restrict__ A_log) {
    __shared__ float pd[LL];
    __shared__ float du[LL];
    __shared__ float ysw[8][LL];
    __shared__ float wsum[9];
    const int bd = blockIdx.x;
    const int b = bd / DM, d = bd - b * DM;
    const int tid = threadIdx.x, lane = tid & 31, wrp = tid >> 5;
    const float* dT  = g_deltaT + (size_t)bd * LL;
    const float* duT = g_duT    + (size_t)bd * LL;

    float4 v = ((const float4*)dT)[tid];
    ((float4*)du)[tid] = ((const float4*)duT)[tid];
    float s0 = v.x, s1 = s0 + v.y, s2 = s1 + v.z, s3 = s2 + v.w;
    float ts = s3;
#pragma unroll
    for (int o = 1; o < 32; o <<= 1) {
        float nv = __shfl_up_sync(0xffffffffu, ts, o);
        if (lane >= o) ts += nv;
    }
    if (lane == 31) wsum[wrp] = ts;
#pragma unroll
    for (int k = 0; k < LL / 32 / 4; k++)
        ((float4*)ysw[wrp])[lane + k * 32] = make_float4(0.f, 0.f, 0.f, 0.f);
    __syncthreads();
    if (tid == 0) {
        float a = 0.f;
#pragma unroll
        for (int i = 0; i < 8; i++) { float x = wsum[i]; wsum[i] = a; a += x; }
        wsum[8] = a;
    }
    __syncthreads();
    float base = wsum[wrp] + ts - s3;
    pd[tid * 4 + 0] = base + s0;
    pd[tid * 4 + 1] = base + s1;
    pd[tid * 4 + 2] = base + s2;
    pd[tid * 4 + 3] = base + s3;
    const float S = wsum[8];
    __syncthreads();

    const int n0 = wrp, n1 = wrp + 8;
    const float An0 = -__expf(A_log[d * NS + n0]);
    const float An1 = -__expf(A_log[d * NS + n1]);
    const float* B0p = g_bcT + ((size_t)b * 2 * NS + n0) * LL;
    const float* C0p = g_bcT + ((size_t)b * 2 * NS + NS + n0) * LL;
    const float* B1p = g_bcT + ((size_t)b * 2 * NS + n1) * LL;
    const float* C1p = g_bcT + ((size_t)b * 2 * NS + NS + n1) * LL;
    float carry0 = 0.f, carry1 = 0.f;

#pragma unroll
    for (int j = 0; j < 8; j++) {
        const int t = j * 128 + lane * 4;
        float dv[4], pv[4], b0[4], c0[4], b1[4], c1[4];
        *(float4*)dv = *(const float4*)&du[t];
        *(float4*)pv = *(const float4*)&pd[t];
        *(float4*)b0 = *(const float4*)&B0p[t];
        *(float4*)c0 = *(const float4*)&C0p[t];
        *(float4*)b1 = *(const float4*)&B1p[t];
        *(float4*)c1 = *(const float4*)&C1p[t];

        float e0[4], e1[4], p0[4], p1[4];
#pragma unroll
        for (int q = 0; q < 4; q++) {
            e0[q] = __expf(An0 * (S - pv[q]));
            e1[q] = __expf(An1 * (S - pv[q]));
            float z0 = dv[q] * b0[q] * e0[q];
            float z1 = dv[q] * b1[q] * e1[q];
            p0[q] = q ? (p0[q - 1] + z0) : z0;
            p1[q] = q ? (p1[q - 1] + z1) : z1;
        }
        float t0 = p0[3], t1 = p1[3];
#pragma unroll
        for (int o = 1; o < 32; o <<= 1) {
            float a0 = __shfl_up_sync(0xffffffffu, t0, o);
            float a1 = __shfl_up_sync(0xffffffffu, t1, o);
            if (lane >= o) { t0 += a0; t1 += a1; }
        }
        const float bs0 = carry0 + t0 - p0[3];
        const float bs1 = carry1 + t1 - p1[3];
        carry0 += __shfl_sync(0xffffffffu, t0, 31);
        carry1 += __shfl_sync(0xffffffffu, t1, 31);

        float acc4[4];
        *(float4*)acc4 = *(const float4*)&ysw[wrp][t];
#pragma unroll
        for (int q = 0; q < 4; q++) {
            float x0 = (bs0 + p0[q]) / (e0[q] + 1e-12f);
            float x1 = (bs1 + p1[q]) / (e1[q] + 1e-12f);
            acc4[q] += x0 * c0[q] + x1 * c1[q];
        }
        *(float4*)&ysw[wrp][t] = *(const float4*)acc4;
    }
    __syncthreads();

    float4 r = ((const float4*)ysw[0])[tid];
#pragma unroll
    for (int w = 1; w < 8; w++) {
        float4 q = ((const float4*)ysw[w])[tid];
        r.x += q.x; r.y += q.y; r.z += q.z; r.w += q.w;
    }
    ((float4*)(g_yT + (size_t)bd * LL))[tid] = r;
}

// ---------------------------------------------------------------------------
// Transpose back + gate + bf16 split of y
// ---------------------------------------------------------------------------
__global__ __launch_bounds__(256)
void back_gate_kernel(const float* __restrict__ D_param) {
    __shared__ float tl[32][33];
    const int r0 = blockIdx.x * 32, d0 = blockIdx.y * 32;
    const int b = r0 / LL, tb = r0 % LL;
#pragma unroll
    for (int j = 0; j < 4; j++) {
        int d = d0 + threadIdx.y + j * 8;
        tl[threadIdx.y + j * 8][threadIdx.x] =
            g_yT[((size_t)b * DM + d) * LL + tb + threadIdx.x];
    }
    __syncthreads();
#pragma unroll
    for (int j = 0; j < 4; j++) {
        int row = r0 + threadIdx.y + j * 8;
        int d = d0 + threadIdx.x;
        float v = tl[threadIdx.x][threadIdx.y + j * 8];
        float uu = g_u[(size_t)row * DM + d];
        float sr = g_sres[(size_t)row * DM + d];
        float y = (v + uu * D_param[d]) * sr;
        __nv_bfloat16 h, l;
        split_bf16(y, h, l);
        g_yhi[(size_t)row * DM + d] = h;
        g_ylo[(size_t)row * DM + d] = l;
    }
}

// ---------------------------------------------------------------------------
extern "C" void kernel_launch(void* const* d_in, const int* in_sizes, int n_in,
                              void* d_out, int out_size) {
    const float* x       = (const float*)d_in[0];
    const float* W_in    = (const float*)d_in[1];
    const float* conv_w  = (const float*)d_in[2];
    const float* conv_b  = (const float*)d_in[3];
    const float* W_x     = (const float*)d_in[4];
    const float* W_delta = (const float*)d_in[5];
    const float* b_delta = (const float*)d_in[6];
    const float* A_log   = (const float*)d_in[7];
    const float* D_param = (const float*)d_in[8];
    const float* W_out   = (const float*)d_in[9];
    float* out = (float*)d_out;

    cudaFuncSetAttribute(hgemm<0>, cudaFuncAttributeMaxDynamicSharedMemorySize, HG_SMEM);
    cudaFuncSetAttribute(hgemm<1>, cudaFuncAttributeMaxDynamicSharedMemorySize, HG_SMEM);
    cudaFuncSetAttribute(hgemm<2>, cudaFuncAttributeMaxDynamicSharedMemorySize, HG_SMEM);
    cudaFuncSetAttribute(hgemm<3>, cudaFuncAttributeMaxDynamicSharedMemorySize, HG_SMEM);

    float* p_delta;
    cudaGetSymbolAddress((void**)&p_delta, g_delta);
    __nv_bfloat16 *p_xhi, *p_xlo, *p_uhi, *p_ulo, *p_yhi, *p_ylo, *p_xphi, *p_xplo;
    __nv_bfloat16 *p_wihi, *p_wilo, *p_wohi, *p_wolo, *p_wxhi, *p_wxlo, *p_wdhi, *p_wdlo;
    cudaGetSymbolAddress((void**)&p_xhi, g_xhi);
    cudaGetSymbolAddress((void**)&p_xlo, g_xlo);
    cudaGetSymbolAddress((void**)&p_uhi, g_uhi);
    cudaGetSymbolAddress((void**)&p_ulo, g_ulo);
    cudaGetSymbolAddress((void**)&p_yhi, g_yhi);
    cudaGetSymbolAddress((void**)&p_ylo, g_ylo);
    cudaGetSymbolAddress((void**)&p_xphi, g_xphi);
    cudaGetSymbolAddress((void**)&p_xplo, g_xplo);
    cudaGetSymbolAddress((void**)&p_wihi, g_wihi);
    cudaGetSymbolAddress((void**)&p_wilo, g_wilo);
    cudaGetSymbolAddress((void**)&p_wohi, g_wohi);
    cudaGetSymbolAddress((void**)&p_wolo, g_wolo);
    cudaGetSymbolAddress((void**)&p_wxhi, g_wxhi);
    cudaGetSymbolAddress((void**)&p_wxlo, g_wxlo);
    cudaGetSymbolAddress((void**)&p_wdhi, g_wdhi);
    cudaGetSymbolAddress((void**)&p_wdlo, g_wdlo);

    // 0) all prep in one launch
    prep_all_kernel<<<PREP_BLKS, 256>>>(x, W_in, W_out, W_x, W_delta);
    // 1) gemm1: x @ W_in -> xs0 | silu(res)
    hgemm<1><<<dim3(ML / 128, (2 * DM) / 64), 256, HG_SMEM>>>(
        p_xhi, p_xlo, p_wihi, p_wilo, nullptr, nullptr, 2 * DM, DM);
    // 2) conv + silu -> u (+ split)
    conv_silu_kernel<<<(ML * DM + 255) / 256, 256>>>(conv_w, conv_b);
    // 3) gemm_x: u @ W_x -> xphi/xplo + bcT
    hgemm<3><<<dim3(ML / 128, 2), 256, HG_SMEM>>>(
        p_uhi, p_ulo, p_wxhi, p_wxlo, nullptr, nullptr, XPW, DM);
    // 4) delta: xp48 @ W_delta (+bias, softplus, clip)
    hgemm<2><<<dim3(ML / 128, DM / 64), 256, HG_SMEM>>>(
        p_xphi, p_xplo, p_wdhi, p_wdlo, p_delta, b_delta, DM, 64);
    // 5) transpose, scan, gate
    trans_fwd_kernel<<<dim3(ML / 32, DM / 32), dim3(32, 8)>>>();
    scan_par_kernel<<<BB * DM, 256>>>(A_log);
    back_gate_kernel<<<dim3(ML / 32, DM / 32), dim3(32, 8)>>>(D_param);
    // 6) out = y @ W_out
    hgemm<0><<<dim3(ML / 128, DM / 64), 256, HG_SMEM>>>(
        p_yhi, p_ylo, p_wohi, p_wolo, out, nullptr, DM, DM);
}

// round 7
// speedup vs baseline: 5.3840x; 1.0706x over previous
#include <cuda_runtime.h>
#include <cuda_bf16.h>
#include <cstdint>
#include <math.h>

#define BB 2
#define LL 1024
#define DM 768
#define NS 16
#define KC 4
#define DR 48
#define ML (BB*LL)          // 2048 rows
#define XPW (DR + 2*NS)     // 80
#define XSPL 6              // split-K factor for gemm_x

// ---------------- scratch (device globals; allocation forbidden) ----------
__device__ float g_xs0[ML*DM];
__device__ float g_sres[ML*DM];
__device__ float g_u[ML*DM];
__device__ float g_delta[ML*DM];
__device__ float g_deltaT[ML*DM];     // (b,d,t)
__device__ float g_duT[ML*DM];        // (b,d,t) delta*u
__device__ float g_yT[ML*DM];         // (b,d,t) scan out
__device__ float g_bcT[BB*2*NS*LL];   // (b, ch, t): ch 0..15 = B, 16..31 = C
__device__ float g_xpp[XSPL*ML*XPW];  // split-K partials for gemm_x

// bf16 hi/lo operands for HMMA GEMMs
__device__ __nv_bfloat16 g_xhi[ML*DM],  g_xlo[ML*DM];       // x split  [M][768]
__device__ __nv_bfloat16 g_uhi[ML*DM],  g_ulo[ML*DM];       // u split  [M][768]
__device__ __nv_bfloat16 g_yhi[ML*DM],  g_ylo[ML*DM];       // y split  [M][768]
__device__ __nv_bfloat16 g_xphi[ML*64], g_xplo[ML*64];      // xp[:, :48] split (cols 48..63 stay 0)
__device__ __nv_bfloat16 g_wihi[2*DM*DM], g_wilo[2*DM*DM];  // W_in^T  [1536][768]
__device__ __nv_bfloat16 g_wohi[DM*DM],   g_wolo[DM*DM];    // W_out^T [768][768]
__device__ __nv_bfloat16 g_wxhi[XPW*DM],  g_wxlo[XPW*DM];   // W_x^T   [80][768]
__device__ __nv_bfloat16 g_wdhi[DM*64],   g_wdlo[DM*64];    // W_delta^T [768][64] (cols 48..63 stay 0)

__device__ __forceinline__ float silu_f(float x) {
    return x / (1.0f + __expf(-x));
}
__device__ __forceinline__ uint32_t smem_u32(const void* p) {
    uint32_t a;
    asm("{ .reg .u64 t; cvta.to.shared.u64 t, %1; cvt.u32.u64 %0, t; }" : "=r"(a) : "l"(p));
    return a;
}
#define CP16(dst, src) \
    asm volatile("cp.async.cg.shared.global [%0], [%1], 16;" :: "r"(dst), "l"(src) : "memory")
#define CP_COMMIT() asm volatile("cp.async.commit_group;" ::: "memory")
#define CP_WAIT1()  asm volatile("cp.async.wait_group 1;" ::: "memory")

__device__ __forceinline__ void ldm_x4(uint32_t* r, uint32_t addr) {
    asm volatile("ldmatrix.sync.aligned.m8n8.x4.shared.b16 {%0,%1,%2,%3}, [%4];"
                 : "=r"(r[0]), "=r"(r[1]), "=r"(r[2]), "=r"(r[3]) : "r"(addr));
}
__device__ __forceinline__ void mma16816(float* c, const uint32_t* a, const uint32_t* b) {
    asm volatile(
        "mma.sync.aligned.m16n8k16.row.col.f32.bf16.bf16.f32 "
        "{%0,%1,%2,%3}, {%4,%5,%6,%7}, {%8,%9}, {%0,%1,%2,%3};"
        : "+f"(c[0]), "+f"(c[1]), "+f"(c[2]), "+f"(c[3])
        : "r"(a[0]), "r"(a[1]), "r"(a[2]), "r"(a[3]), "r"(b[0]), "r"(b[1]));
}
__device__ __forceinline__ void split_bf16(float x, __nv_bfloat16& h, __nv_bfloat16& l) {
    h = __float2bfloat16(x);
    l = __float2bfloat16(x - __bfloat162float(h));
}

// ---------------------------------------------------------------------------
// HMMA GEMM (bf16 two-term split, 3 product terms): C = A * B^T
//   CTA tile 128x64xBK32, 8 warps (2x4), 3-stage cp.async pipeline.
//   EPI 0: plain store. EPI 1: gemm1 split. EPI 2: softplus/clip.
//   EPI 4: split-K partial (gridDim.z chunks of ksplit K), store fp32 to
//          C + (z*ML + row)*N + col, guarded col<N.
// ---------------------------------------------------------------------------
#define HG_STRIDE 40                   // bf16 per smem row (32 data + 8 pad)
#define HG_TA (128*HG_STRIDE*2)        // 10240 B
#define HG_TB (64*HG_STRIDE*2)         // 5120 B
#define HG_STAGE (2*HG_TA + 2*HG_TB)   // 30720 B
#define HG_NSTG 3
#define HG_SMEM (HG_NSTG*HG_STAGE)     // 92160 B

template<int EPI>
__global__ __launch_bounds__(256, 2)
void hgemm(const __nv_bfloat16* __restrict__ Ahi, const __nv_bfloat16* __restrict__ Alo,
           const __nv_bfloat16* __restrict__ Bhi, const __nv_bfloat16* __restrict__ Blo,
           float* __restrict__ C, const float* __restrict__ bias, int N, int K,
           int ksplit) {
    extern __shared__ char hsm[];
    const uint32_t sb = smem_u32(hsm);
    const int tid = threadIdx.x;
    const int lane = tid & 31, wid = tid >> 5;
    const int wm = wid >> 2, wn = wid & 3;         // 2 (m) x 4 (n)
    const int bm = blockIdx.x * 128, bn = blockIdx.y * 64;

    int kcnt = K;
    if (EPI == 4) {
        kcnt = ksplit;
        const int ko = blockIdx.z * ksplit;
        Ahi += ko; Alo += ko; Bhi += ko; Blo += ko;
        C += (size_t)blockIdx.z * ML * N;
    }

    float acc[4][2][4];
#pragma unroll
    for (int i = 0; i < 4; i++)
#pragma unroll
        for (int j = 0; j < 2; j++)
#pragma unroll
            for (int q = 0; q < 4; q++) acc[i][j][q] = 0.f;

    const int lr = tid >> 2;       // 0..63
    const int lc = (tid & 3) * 8;  // 0,8,16,24
    const bool bvalid = (bn + lr) < N;

    auto issue = [&](int c, int s) {
        const int k0 = c * 32;
        const uint32_t st = sb + s * HG_STAGE;
#pragma unroll
        for (int h = 0; h < 2; h++) {
            const int row = lr + h * 64;
            const uint32_t so = (uint32_t)(row * HG_STRIDE + lc) * 2;
            const size_t ga = (size_t)(bm + row) * K + k0 + lc;
            CP16(st + so, Ahi + ga);
            CP16(st + HG_TA + so, Alo + ga);
        }
        const uint32_t so = (uint32_t)(lr * HG_STRIDE + lc) * 2;
        if (bvalid) {
            const size_t gb = (size_t)(bn + lr) * K + k0 + lc;
            CP16(st + 2 * HG_TA + so, Bhi + gb);
            CP16(st + 2 * HG_TA + HG_TB + so, Blo + gb);
        } else {
            *(uint4*)(hsm + s * HG_STAGE + 2 * HG_TA + so) = make_uint4(0, 0, 0, 0);
            *(uint4*)(hsm + s * HG_STAGE + 2 * HG_TA + HG_TB + so) = make_uint4(0, 0, 0, 0);
        }
    };

    const int nch = kcnt / 32;
    issue(0, 0);
    CP_COMMIT();
    if (nch > 1) { issue(1, 1); }
    CP_COMMIT();

    const int a_r = lane & 15;
    const int a_k = (lane >> 4) * 8;
    const int b_row = ((lane >> 4) & 1) * 8 + (lane & 7);
    const int b_kk = ((lane >> 3) & 1) * 8;

    for (int c = 0; c < nch; c++) {
        CP_WAIT1();
        __syncthreads();
        if (c + 2 < nch) issue(c + 2, (c + 2) % HG_NSTG);
        CP_COMMIT();

        const uint32_t st = sb + (c % HG_NSTG) * HG_STAGE;
#pragma unroll
        for (int ks = 0; ks < 32; ks += 16) {
            uint32_t ah[4][4], al[4][4], bh[4], bl[4];
#pragma unroll
            for (int ma = 0; ma < 4; ma++) {
                const uint32_t off =
                    (uint32_t)((wm * 64 + ma * 16 + a_r) * HG_STRIDE + ks + a_k) * 2;
                ldm_x4(ah[ma], st + off);
                ldm_x4(al[ma], st + HG_TA + off);
            }
            {
                const uint32_t off =
                    (uint32_t)((wn * 16 + b_row) * HG_STRIDE + ks + b_kk) * 2;
                ldm_x4(bh, st + 2 * HG_TA + off);
                ldm_x4(bl, st + 2 * HG_TA + HG_TB + off);
            }
#pragma unroll
            for (int ma = 0; ma < 4; ma++)
#pragma unroll
                for (int na = 0; na < 2; na++) {
                    mma16816(acc[ma][na], ah[ma], bh + na * 2);
                    mma16816(acc[ma][na], ah[ma], bl + na * 2);
                    mma16816(acc[ma][na], al[ma], bh + na * 2);
                }
        }
    }

    // epilogue
    const int eg = lane >> 2, ei = lane & 3;
#pragma unroll
    for (int ma = 0; ma < 4; ma++) {
#pragma unroll
        for (int na = 0; na < 2; na++) {
            const int col = bn + wn * 16 + na * 8 + ei * 2;
#pragma unroll
            for (int h = 0; h < 2; h++) {
                const int row = bm + wm * 64 + ma * 16 + eg + h * 8;
                const float v0 = acc[ma][na][h * 2 + 0];
                const float v1 = acc[ma][na][h * 2 + 1];
                if (EPI == 0) {
                    *(float2*)(&C[(size_t)row * N + col]) = make_float2(v0, v1);
                } else if (EPI == 1) {
                    if (col < DM)
                        *(float2*)(&g_xs0[(size_t)row * DM + col]) = make_float2(v0, v1);
                    else
                        *(float2*)(&g_sres[(size_t)row * DM + (col - DM)]) =
                            make_float2(silu_f(v0), silu_f(v1));
                } else if (EPI == 2) {
                    float o[2];
#pragma unroll
                    for (int q = 0; q < 2; q++) {
                        float v = (q ? v1 : v0) + bias[col + q];
                        float sp = (v > 0.f) ? (v + log1pf(__expf(-v))) : log1pf(__expf(v));
                        o[q] = fminf(fmaxf(sp, 1e-4f), 0.1f);
                    }
                    *(float2*)(&C[(size_t)row * DM + col]) = make_float2(o[0], o[1]);
                } else {   // EPI 4: split-K partial, cols guarded by N
                    if (col + 1 < N)
                        *(float2*)(&C[(size_t)row * N + col]) = make_float2(v0, v1);
                    else if (col < N)
                        C[(size_t)row * N + col] = v0;
                }
            }
        }
    }
}

// ---------------------------------------------------------------------------
// Split-K reduce for gemm_x: sum 6 partials; cols<48 -> bf16 split to xphi/xplo;
// cols 48..79 -> scatter to bcT.
// ---------------------------------------------------------------------------
__global__ __launch_bounds__(256)
void reduce_xp_kernel() {
    const int idx = blockIdx.x * blockDim.x + threadIdx.x;   // < ML*XPW
    float s = 0.f;
#pragma unroll
    for (int z = 0; z < XSPL; z++) s += g_xpp[(size_t)z * ML * XPW + idx];
    const int cc = idx % XPW;
    const int row = idx / XPW;
    if (cc < DR) {
        __nv_bfloat16 hh, ll;
        split_bf16(s, hh, ll);
        g_xphi[(size_t)row * 64 + cc] = hh;
        g_xplo[(size_t)row * 64 + cc] = ll;
    } else {
        const int b = row / LL, t = row % LL;
        g_bcT[((size_t)b * 2 * NS + (cc - DR)) * LL + t] = s;
    }
}

// ---------------------------------------------------------------------------
// Fused prep: x split + all 4 weight transposes in one launch.
// ---------------------------------------------------------------------------
__device__ __forceinline__ void wtrans_tile(const float* __restrict__ W,
                                            __nv_bfloat16* __restrict__ Whi,
                                            __nv_bfloat16* __restrict__ Wlo,
                                            int Kdim, int Ndim, int ldout,
                                            int kb, int nb) {
    __shared__ float tl[32][33];
    const int k0 = kb * 32, n0 = nb * 32;
    const int tx = threadIdx.x & 31, ty = threadIdx.x >> 5;
#pragma unroll
    for (int j = 0; j < 4; j++) {
        int k = k0 + ty + j * 8;
        int n = n0 + tx;
        tl[ty + j * 8][tx] = (k < Kdim && n < Ndim) ? W[(size_t)k * Ndim + n] : 0.f;
    }
    __syncthreads();
#pragma unroll
    for (int j = 0; j < 4; j++) {
        int n = n0 + ty + j * 8;
        int k = k0 + tx;
        if (n < Ndim && k < Kdim) {
            __nv_bfloat16 h, l;
            split_bf16(tl[tx][ty + j * 8], h, l);
            Whi[(size_t)n * ldout + k] = h;
            Wlo[(size_t)n * ldout + k] = l;
        }
    }
}

#define PREP_XBLK (ML*DM/1024)     // 1536
__global__ __launch_bounds__(256)
void prep_all_kernel(const float* __restrict__ x, const float* __restrict__ W_in,
                     const float* __restrict__ W_out, const float* __restrict__ W_x,
                     const float* __restrict__ W_delta) {
    int blk = blockIdx.x;
    if (blk < PREP_XBLK) {
        const int i4 = blk * 256 + threadIdx.x;
        float4 v = ((const float4*)x)[i4];
        __nv_bfloat16 h0, l0, h1, l1, h2, l2, h3, l3;
        split_bf16(v.x, h0, l0); split_bf16(v.y, h1, l1);
        split_bf16(v.z, h2, l2); split_bf16(v.w, h3, l3);
        __nv_bfloat162* ph = (__nv_bfloat162*)g_xhi;
        __nv_bfloat162* pl = (__nv_bfloat162*)g_xlo;
        ph[i4 * 2]     = __nv_bfloat162(h0, h1);
        ph[i4 * 2 + 1] = __nv_bfloat162(h2, h3);
        pl[i4 * 2]     = __nv_bfloat162(l0, l1);
        pl[i4 * 2 + 1] = __nv_bfloat162(l2, l3);
        return;
    }
    blk -= PREP_XBLK;
    if (blk < 1152) { wtrans_tile(W_in, g_wihi, g_wilo, DM, 2 * DM, DM, blk % 24, blk / 24); return; }
    blk -= 1152;
    if (blk < 576)  { wtrans_tile(W_out, g_wohi, g_wolo, DM, DM, DM, blk % 24, blk / 24); return; }
    blk -= 576;
    if (blk < 72)   { wtrans_tile(W_x, g_wxhi, g_wxlo, DM, XPW, DM, blk % 24, blk / 24); return; }
    blk -= 72;
    wtrans_tile(W_delta, g_wdhi, g_wdlo, DR, DM, 64, blk % 2, blk / 2);
}
#define PREP_BLKS (PREP_XBLK + 1152 + 576 + 72 + 48)

// ---------------------------------------------------------------------------
// Depthwise causal conv + bias + SiLU -> u (+ bf16 split)
// ---------------------------------------------------------------------------
__global__ __launch_bounds__(256)
void conv_silu_kernel(const float* __restrict__ conv_w, const float* __restrict__ conv_b) {
    int idx = blockIdx.x * blockDim.x + threadIdx.x;
    if (idx >= ML * DM) return;
    int d = idx % DM;
    int t = (idx / DM) % LL;
    int base = idx - t * DM - d;
    float acc = conv_b[d];
#pragma unroll
    for (int k = 0; k < KC; k++) {
        int tt = t - (KC - 1) + k;
        if (tt >= 0)
            acc = fmaf(conv_w[d * KC + k], g_xs0[base + tt * DM + d], acc);
    }
    float u = silu_f(acc);
    g_u[idx] = u;
    split_bf16(u, g_uhi[idx], g_ulo[idx]);
}

// ---------------------------------------------------------------------------
// Transpose fwd: delta, delta*u -> (b,d,t)
// ---------------------------------------------------------------------------
__global__ __launch_bounds__(256)
void trans_fwd_kernel() {
    __shared__ float t0[32][33];
    __shared__ float t1[32][33];
    const int r0 = blockIdx.x * 32, d0 = blockIdx.y * 32;
    const int b = r0 / LL, tb = r0 % LL;
#pragma unroll
    for (int j = 0; j < 4; j++) {
        int row = r0 + threadIdx.y + j * 8;
        int d = d0 + threadIdx.x;
        float dl = g_delta[(size_t)row * DM + d];
        float uu = g_u[(size_t)row * DM + d];
        t0[threadIdx.y + j * 8][threadIdx.x] = dl;
        t1[threadIdx.y + j * 8][threadIdx.x] = dl * uu;
    }
    __syncthreads();
#pragma unroll
    for (int j = 0; j < 4; j++) {
        int d = d0 + threadIdx.y + j * 8;
        int t = tb + threadIdx.x;
        g_deltaT[((size_t)b * DM + d) * LL + t] = t0[threadIdx.x][threadIdx.y + j * 8];
        g_duT   [((size_t)b * DM + d) * LL + t] = t1[threadIdx.x][threadIdx.y + j * 8];
    }
}

// ---------------------------------------------------------------------------
// Parallel selective scan. One block per (b,d).
// ---------------------------------------------------------------------------
__global__ __launch_bounds__(256)
void scan_par_kernel(const float* __restrict__ A_log) {
    __shared__ float pd[LL];
    __shared__ float du[LL];
    __shared__ float ysw[8][LL];
    __shared__ float wsum[9];
    const int bd = blockIdx.x;
    const int b = bd / DM, d = bd - b * DM;
    const int tid = threadIdx.x, lane = tid & 31, wrp = tid >> 5;
    const float* dT  = g_deltaT + (size_t)bd * LL;
    const float* duT = g_duT    + (size_t)bd * LL;

    float4 v = ((const float4*)dT)[tid];
    ((float4*)du)[tid] = ((const float4*)duT)[tid];
    float s0 = v.x, s1 = s0 + v.y, s2 = s1 + v.z, s3 = s2 + v.w;
    float ts = s3;
#pragma unroll
    for (int o = 1; o < 32; o <<= 1) {
        float nv = __shfl_up_sync(0xffffffffu, ts, o);
        if (lane >= o) ts += nv;
    }
    if (lane == 31) wsum[wrp] = ts;
    __syncthreads();
    if (tid == 0) {
        float a = 0.f;
#pragma unroll
        for (int i = 0; i < 8; i++) { float x = wsum[i]; wsum[i] = a; a += x; }
        wsum[8] = a;
    }
    __syncthreads();
    float base = wsum[wrp] + ts - s3;
    pd[tid * 4 + 0] = base + s0;
    pd[tid * 4 + 1] = base + s1;
    pd[tid * 4 + 2] = base + s2;
    pd[tid * 4 + 3] = base + s3;
    const float S = wsum[8];
    __syncthreads();

    const int n0 = wrp, n1 = wrp + 8;
    const float An0 = -__expf(A_log[d * NS + n0]);
    const float An1 = -__expf(A_log[d * NS + n1]);
    const float* B0p = g_bcT + ((size_t)b * 2 * NS + n0) * LL;
    const float* C0p = g_bcT + ((size_t)b * 2 * NS + NS + n0) * LL;
    const float* B1p = g_bcT + ((size_t)b * 2 * NS + n1) * LL;
    const float* C1p = g_bcT + ((size_t)b * 2 * NS + NS + n1) * LL;
    float carry0 = 0.f, carry1 = 0.f;

#pragma unroll
    for (int j = 0; j < 8; j++) {
        const int t = j * 128 + lane * 4;
        float dv[4], pv[4], b0[4], c0[4], b1[4], c1[4];
        *(float4*)dv = *(const float4*)&du[t];
        *(float4*)pv = *(const float4*)&pd[t];
        *(float4*)b0 = *(const float4*)&B0p[t];
        *(float4*)c0 = *(const float4*)&C0p[t];
        *(float4*)b1 = *(const float4*)&B1p[t];
        *(float4*)c1 = *(const float4*)&C1p[t];

        float e0[4], e1[4], p0[4], p1[4];
#pragma unroll
        for (int q = 0; q < 4; q++) {
            e0[q] = __expf(An0 * (S - pv[q]));
            e1[q] = __expf(An1 * (S - pv[q]));
            float z0 = dv[q] * b0[q] * e0[q];
            float z1 = dv[q] * b1[q] * e1[q];
            p0[q] = q ? (p0[q - 1] + z0) : z0;
            p1[q] = q ? (p1[q - 1] + z1) : z1;
        }
        float t0 = p0[3], t1 = p1[3];
#pragma unroll
        for (int o = 1; o < 32; o <<= 1) {
            float a0 = __shfl_up_sync(0xffffffffu, t0, o);
            float a1 = __shfl_up_sync(0xffffffffu, t1, o);
            if (lane >= o) { t0 += a0; t1 += a1; }
        }
        const float bs0 = carry0 + t0 - p0[3];
        const float bs1 = carry1 + t1 - p1[3];
        carry0 += __shfl_sync(0xffffffffu, t0, 31);
        carry1 += __shfl_sync(0xffffffffu, t1, 31);

        float acc4[4];
#pragma unroll
        for (int q = 0; q < 4; q++) {
            float x0 = (bs0 + p0[q]) / (e0[q] + 1e-12f);
            float x1 = (bs1 + p1[q]) / (e1[q] + 1e-12f);
            acc4[q] = x0 * c0[q] + x1 * c1[q];
        }
        *(float4*)&ysw[wrp][t] = *(const float4*)acc4;
    }
    __syncthreads();

    float4 r = ((const float4*)ysw[0])[tid];
#pragma unroll
    for (int w = 1; w < 8; w++) {
        float4 q = ((const float4*)ysw[w])[tid];
        r.x += q.x; r.y += q.y; r.z += q.z; r.w += q.w;
    }
    ((float4*)(g_yT + (size_t)bd * LL))[tid] = r;
}

// ---------------------------------------------------------------------------
// Transpose back + gate + bf16 split of y
// ---------------------------------------------------------------------------
__global__ __launch_bounds__(256)
void back_gate_kernel(const float* __restrict__ D_param) {
    __shared__ float tl[32][33];
    const int r0 = blockIdx.x * 32, d0 = blockIdx.y * 32;
    const int b = r0 / LL, tb = r0 % LL;
#pragma unroll
    for (int j = 0; j < 4; j++) {
        int d = d0 + threadIdx.y + j * 8;
        tl[threadIdx.y + j * 8][threadIdx.x] =
            g_yT[((size_t)b * DM + d) * LL + tb + threadIdx.x];
    }
    __syncthreads();
#pragma unroll
    for (int j = 0; j < 4; j++) {
        int row = r0 + threadIdx.y + j * 8;
        int d = d0 + threadIdx.x;
        float v = tl[threadIdx.x][threadIdx.y + j * 8];
        float uu = g_u[(size_t)row * DM + d];
        float sr = g_sres[(size_t)row * DM + d];
        float y = (v + uu * D_param[d]) * sr;
        __nv_bfloat16 h, l;
        split_bf16(y, h, l);
        g_yhi[(size_t)row * DM + d] = h;
        g_ylo[(size_t)row * DM + d] = l;
    }
}

// ---------------------------------------------------------------------------
extern "C" void kernel_launch(void* const* d_in, const int* in_sizes, int n_in,
                              void* d_out, int out_size) {
    const float* x       = (const float*)d_in[0];
    const float* W_in    = (const float*)d_in[1];
    const float* conv_w  = (const float*)d_in[2];
    const float* conv_b  = (const float*)d_in[3];
    const float* W_x     = (const float*)d_in[4];
    const float* W_delta = (const float*)d_in[5];
    const float* b_delta = (const float*)d_in[6];
    const float* A_log   = (const float*)d_in[7];
    const float* D_param = (const float*)d_in[8];
    const float* W_out   = (const float*)d_in[9];
    float* out = (float*)d_out;

    cudaFuncSetAttribute(hgemm<0>, cudaFuncAttributeMaxDynamicSharedMemorySize, HG_SMEM);
    cudaFuncSetAttribute(hgemm<1>, cudaFuncAttributeMaxDynamicSharedMemorySize, HG_SMEM);
    cudaFuncSetAttribute(hgemm<2>, cudaFuncAttributeMaxDynamicSharedMemorySize, HG_SMEM);
    cudaFuncSetAttribute(hgemm<4>, cudaFuncAttributeMaxDynamicSharedMemorySize, HG_SMEM);

    float *p_delta, *p_xpp;
    cudaGetSymbolAddress((void**)&p_delta, g_delta);
    cudaGetSymbolAddress((void**)&p_xpp,   g_xpp);
    __nv_bfloat16 *p_xhi, *p_xlo, *p_uhi, *p_ulo, *p_yhi, *p_ylo, *p_xphi, *p_xplo;
    __nv_bfloat16 *p_wihi, *p_wilo, *p_wohi, *p_wolo, *p_wxhi, *p_wxlo, *p_wdhi, *p_wdlo;
    cudaGetSymbolAddress((void**)&p_xhi, g_xhi);
    cudaGetSymbolAddress((void**)&p_xlo, g_xlo);
    cudaGetSymbolAddress((void**)&p_uhi, g_uhi);
    cudaGetSymbolAddress((void**)&p_ulo, g_ulo);
    cudaGetSymbolAddress((void**)&p_yhi, g_yhi);
    cudaGetSymbolAddress((void**)&p_ylo, g_ylo);
    cudaGetSymbolAddress((void**)&p_xphi, g_xphi);
    cudaGetSymbolAddress((void**)&p_xplo, g_xplo);
    cudaGetSymbolAddress((void**)&p_wihi, g_wihi);
    cudaGetSymbolAddress((void**)&p_wilo, g_wilo);
    cudaGetSymbolAddress((void**)&p_wohi, g_wohi);
    cudaGetSymbolAddress((void**)&p_wolo, g_wolo);
    cudaGetSymbolAddress((void**)&p_wxhi, g_wxhi);
    cudaGetSymbolAddress((void**)&p_wxlo, g_wxlo);
    cudaGetSymbolAddress((void**)&p_wdhi, g_wdhi);
    cudaGetSymbolAddress((void**)&p_wdlo, g_wdlo);

    // 0) all prep in one launch
    prep_all_kernel<<<PREP_BLKS, 256>>>(x, W_in, W_out, W_x, W_delta);
    // 1) gemm1: x @ W_in -> xs0 | silu(res)
    hgemm<1><<<dim3(ML / 128, (2 * DM) / 64), 256, HG_SMEM>>>(
        p_xhi, p_xlo, p_wihi, p_wilo, nullptr, nullptr, 2 * DM, DM, 0);
    // 2) conv + silu -> u (+ split)
    conv_silu_kernel<<<(ML * DM + 255) / 256, 256>>>(conv_w, conv_b);
    // 3) gemm_x split-K=6: u @ W_x -> partials
    hgemm<4><<<dim3(ML / 128, 2, XSPL), 256, HG_SMEM>>>(
        p_uhi, p_ulo, p_wxhi, p_wxlo, p_xpp, nullptr, XPW, DM, DM / XSPL);
    // 3b) reduce partials -> xphi/xplo + bcT
    reduce_xp_kernel<<<(ML * XPW) / 256, 256>>>();
    // 4) delta: xp48 @ W_delta (+bias, softplus, clip)
    hgemm<2><<<dim3(ML / 128, DM / 64), 256, HG_SMEM>>>(
        p_xphi, p_xplo, p_wdhi, p_wdlo, p_delta, b_delta, DM, 64, 0);
    // 5) transpose, scan, gate
    trans_fwd_kernel<<<dim3(ML / 32, DM / 32), dim3(32, 8)>>>();
    scan_par_kernel<<<BB * DM, 256>>>(A_log);
    back_gate_kernel<<<dim3(ML / 32, DM / 32), dim3(32, 8)>>>(D_param);
    // 6) out = y @ W_out
    hgemm<0><<<dim3(ML / 128, DM / 64), 256, HG_SMEM>>>(
        p_yhi, p_ylo, p_wohi, p_wolo, out, nullptr, DM, DM, 0);
}

// round 8
// speedup vs baseline: 5.5903x; 1.0383x over previous
#include <cuda_runtime.h>
#include <cuda_bf16.h>
#include <cstdint>
#include <math.h>

#define BB 2
#define LL 1024
#define DM 768
#define NS 16
#define KC 4
#define DR 48
#define ML (BB*LL)          // 2048 rows
#define XPW (DR + 2*NS)     // 80
#define XSPL 6              // split-K factor for gemm_x

// ---------------- scratch (device globals; allocation forbidden) ----------
__device__ float g_xs0[ML*DM];
__device__ float g_sres[ML*DM];
__device__ float g_u[ML*DM];
__device__ float g_delta[ML*DM];
__device__ float g_deltaT[ML*DM];     // (b,d,t)
__device__ float g_duT[ML*DM];        // (b,d,t) delta*u
__device__ float g_yT[ML*DM];         // (b,d,t) scan out
__device__ float g_bcT[BB*2*NS*LL];   // (b, ch, t): ch 0..15 = B, 16..31 = C
__device__ float g_xpp[XSPL*ML*XPW];  // split-K partials for gemm_x

// bf16 hi/lo operands for HMMA GEMMs
__device__ __nv_bfloat16 g_xhi[ML*DM],  g_xlo[ML*DM];       // x split  [M][768]
__device__ __nv_bfloat16 g_uhi[ML*DM],  g_ulo[ML*DM];       // u split  [M][768]
__device__ __nv_bfloat16 g_yhi[ML*DM],  g_ylo[ML*DM];       // y split  [M][768]
__device__ __nv_bfloat16 g_xphi[ML*64], g_xplo[ML*64];      // xp[:, :48] split (cols 48..63 stay 0)
__device__ __nv_bfloat16 g_wihi[2*DM*DM], g_wilo[2*DM*DM];  // W_in^T  [1536][768]
__device__ __nv_bfloat16 g_wohi[DM*DM],   g_wolo[DM*DM];    // W_out^T [768][768]
__device__ __nv_bfloat16 g_wxhi[XPW*DM],  g_wxlo[XPW*DM];   // W_x^T   [80][768]
__device__ __nv_bfloat16 g_wdhi[DM*64],   g_wdlo[DM*64];    // W_delta^T [768][64] (cols 48..63 stay 0)

__device__ __forceinline__ float silu_f(float x) {
    return x / (1.0f + __expf(-x));
}
__device__ __forceinline__ uint32_t smem_u32(const void* p) {
    uint32_t a;
    asm("{ .reg .u64 t; cvta.to.shared.u64 t, %1; cvt.u32.u64 %0, t; }" : "=r"(a) : "l"(p));
    return a;
}
#define CP16(dst, src) \
    asm volatile("cp.async.cg.shared.global [%0], [%1], 16;" :: "r"(dst), "l"(src) : "memory")
#define CP_COMMIT() asm volatile("cp.async.commit_group;" ::: "memory")
#define CP_WAIT1()  asm volatile("cp.async.wait_group 1;" ::: "memory")
#define CP_WAIT0()  asm volatile("cp.async.wait_group 0;" ::: "memory")

__device__ __forceinline__ void ldm_x4(uint32_t* r, uint32_t addr) {
    asm volatile("ldmatrix.sync.aligned.m8n8.x4.shared.b16 {%0,%1,%2,%3}, [%4];"
                 : "=r"(r[0]), "=r"(r[1]), "=r"(r[2]), "=r"(r[3]) : "r"(addr));
}
__device__ __forceinline__ void mma16816(float* c, const uint32_t* a, const uint32_t* b) {
    asm volatile(
        "mma.sync.aligned.m16n8k16.row.col.f32.bf16.bf16.f32 "
        "{%0,%1,%2,%3}, {%4,%5,%6,%7}, {%8,%9}, {%0,%1,%2,%3};"
        : "+f"(c[0]), "+f"(c[1]), "+f"(c[2]), "+f"(c[3])
        : "r"(a[0]), "r"(a[1]), "r"(a[2]), "r"(a[3]), "r"(b[0]), "r"(b[1]));
}
__device__ __forceinline__ void split_bf16(float x, __nv_bfloat16& h, __nv_bfloat16& l) {
    h = __float2bfloat16(x);
    l = __float2bfloat16(x - __bfloat162float(h));
}

// ---------------------------------------------------------------------------
// HMMA GEMM (bf16 two-term split, 3 product terms): C = A * B^T
//   CTA tile 128x64xBK32, 8 warps (2x4), 2-stage cp.async pipeline,
//   3 CTAs/SM (reg-capped). B-frags first, per-ma interleaved A-ldm + MMA.
//   EPI 0: plain. EPI 1: gemm1 split. EPI 2: softplus/clip. EPI 4: split-K.
// ---------------------------------------------------------------------------
#define HG_STRIDE 40                   // bf16 per smem row (32 data + 8 pad)
#define HG_TA (128*HG_STRIDE*2)        // 10240 B
#define HG_TB (64*HG_STRIDE*2)         // 5120 B
#define HG_STAGE (2*HG_TA + 2*HG_TB)   // 30720 B
#define HG_NSTG 2
#define HG_SMEM (HG_NSTG*HG_STAGE)     // 61440 B

template<int EPI>
__global__ __launch_bounds__(256, 3)
void hgemm(const __nv_bfloat16* __restrict__ Ahi, const __nv_bfloat16* __restrict__ Alo,
           const __nv_bfloat16* __restrict__ Bhi, const __nv_bfloat16* __restrict__ Blo,
           float* __restrict__ C, const float* __restrict__ bias, int N, int K,
           int ksplit) {
    extern __shared__ char hsm[];
    const uint32_t sb = smem_u32(hsm);
    const int tid = threadIdx.x;
    const int lane = tid & 31, wid = tid >> 5;
    const int wm = wid >> 2, wn = wid & 3;         // 2 (m) x 4 (n)
    const int bm = blockIdx.x * 128, bn = blockIdx.y * 64;

    int kcnt = K;
    if (EPI == 4) {
        kcnt = ksplit;
        const int ko = blockIdx.z * ksplit;
        Ahi += ko; Alo += ko; Bhi += ko; Blo += ko;
        C += (size_t)blockIdx.z * ML * N;
    }

    float acc[4][2][4];
#pragma unroll
    for (int i = 0; i < 4; i++)
#pragma unroll
        for (int j = 0; j < 2; j++)
#pragma unroll
            for (int q = 0; q < 4; q++) acc[i][j][q] = 0.f;

    const int lr = tid >> 2;       // 0..63
    const int lc = (tid & 3) * 8;  // 0,8,16,24
    const bool bvalid = (bn + lr) < N;

    auto issue = [&](int c, int s) {
        const int k0 = c * 32;
        const uint32_t st = sb + s * HG_STAGE;
#pragma unroll
        for (int h = 0; h < 2; h++) {
            const int row = lr + h * 64;
            const uint32_t so = (uint32_t)(row * HG_STRIDE + lc) * 2;
            const size_t ga = (size_t)(bm + row) * K + k0 + lc;
            CP16(st + so, Ahi + ga);
            CP16(st + HG_TA + so, Alo + ga);
        }
        const uint32_t so = (uint32_t)(lr * HG_STRIDE + lc) * 2;
        if (bvalid) {
            const size_t gb = (size_t)(bn + lr) * K + k0 + lc;
            CP16(st + 2 * HG_TA + so, Bhi + gb);
            CP16(st + 2 * HG_TA + HG_TB + so, Blo + gb);
        } else {
            *(uint4*)(hsm + s * HG_STAGE + 2 * HG_TA + so) = make_uint4(0, 0, 0, 0);
            *(uint4*)(hsm + s * HG_STAGE + 2 * HG_TA + HG_TB + so) = make_uint4(0, 0, 0, 0);
        }
    };

    const int nch = kcnt / 32;
    issue(0, 0);
    CP_COMMIT();

    const int a_r = lane & 15;
    const int a_k = (lane >> 4) * 8;
    const int b_row = ((lane >> 4) & 1) * 8 + (lane & 7);
    const int b_kk = ((lane >> 3) & 1) * 8;

    for (int c = 0; c < nch; c++) {
        if (c + 1 < nch) {
            issue(c + 1, (c + 1) & 1);
            CP_COMMIT();
            CP_WAIT1();            // group c complete; c+1 still in flight
        } else {
            CP_WAIT0();
        }
        __syncthreads();

        const uint32_t st = sb + (c & 1) * HG_STAGE;
#pragma unroll
        for (int ks = 0; ks < 32; ks += 16) {
            // B frags FIRST (first MMA depends on them)
            uint32_t bh[4], bl[4];
            {
                const uint32_t off =
                    (uint32_t)((wn * 16 + b_row) * HG_STRIDE + ks + b_kk) * 2;
                ldm_x4(bh, st + 2 * HG_TA + off);
                ldm_x4(bl, st + 2 * HG_TA + HG_TB + off);
            }
            // per-ma: load frags then immediately use them; ma+1 LDSM overlaps ma MMAs
#pragma unroll
            for (int ma = 0; ma < 4; ma++) {
                const uint32_t off =
                    (uint32_t)((wm * 64 + ma * 16 + a_r) * HG_STRIDE + ks + a_k) * 2;
                uint32_t ah[4], al[4];
                ldm_x4(ah, st + off);
                ldm_x4(al, st + HG_TA + off);
                mma16816(acc[ma][0], ah, bh);
                mma16816(acc[ma][1], ah, bh + 2);
                mma16816(acc[ma][0], ah, bl);
                mma16816(acc[ma][1], ah, bl + 2);
                mma16816(acc[ma][0], al, bh);
                mma16816(acc[ma][1], al, bh + 2);
            }
        }
        __syncthreads();           // stage reusable for issue(c+2)
    }

    // epilogue
    const int eg = lane >> 2, ei = lane & 3;
#pragma unroll
    for (int ma = 0; ma < 4; ma++) {
#pragma unroll
        for (int na = 0; na < 2; na++) {
            const int col = bn + wn * 16 + na * 8 + ei * 2;
#pragma unroll
            for (int h = 0; h < 2; h++) {
                const int row = bm + wm * 64 + ma * 16 + eg + h * 8;
                const float v0 = acc[ma][na][h * 2 + 0];
                const float v1 = acc[ma][na][h * 2 + 1];
                if (EPI == 0) {
                    *(float2*)(&C[(size_t)row * N + col]) = make_float2(v0, v1);
                } else if (EPI == 1) {
                    if (col < DM)
                        *(float2*)(&g_xs0[(size_t)row * DM + col]) = make_float2(v0, v1);
                    else
                        *(float2*)(&g_sres[(size_t)row * DM + (col - DM)]) =
                            make_float2(silu_f(v0), silu_f(v1));
                } else if (EPI == 2) {
                    float o[2];
#pragma unroll
                    for (int q = 0; q < 2; q++) {
                        float v = (q ? v1 : v0) + bias[col + q];
                        float sp = (v > 0.f) ? (v + log1pf(__expf(-v))) : log1pf(__expf(v));
                        o[q] = fminf(fmaxf(sp, 1e-4f), 0.1f);
                    }
                    *(float2*)(&C[(size_t)row * DM + col]) = make_float2(o[0], o[1]);
                } else {   // EPI 4: split-K partial, cols guarded by N
                    if (col + 1 < N)
                        *(float2*)(&C[(size_t)row * N + col]) = make_float2(v0, v1);
                    else if (col < N)
                        C[(size_t)row * N + col] = v0;
                }
            }
        }
    }
}

// ---------------------------------------------------------------------------
// Split-K reduce for gemm_x
// ---------------------------------------------------------------------------
__global__ __launch_bounds__(256)
void reduce_xp_kernel() {
    const int idx = blockIdx.x * blockDim.x + threadIdx.x;   // < ML*XPW
    float s = 0.f;
#pragma unroll
    for (int z = 0; z < XSPL; z++) s += g_xpp[(size_t)z * ML * XPW + idx];
    const int cc = idx % XPW;
    const int row = idx / XPW;
    if (cc < DR) {
        __nv_bfloat16 hh, ll;
        split_bf16(s, hh, ll);
        g_xphi[(size_t)row * 64 + cc] = hh;
        g_xplo[(size_t)row * 64 + cc] = ll;
    } else {
        const int b = row / LL, t = row % LL;
        g_bcT[((size_t)b * 2 * NS + (cc - DR)) * LL + t] = s;
    }
}

// ---------------------------------------------------------------------------
// Fused prep: x split + all 4 weight transposes in one launch.
// ---------------------------------------------------------------------------
__device__ __forceinline__ void wtrans_tile(const float* __restrict__ W,
                                            __nv_bfloat16* __restrict__ Whi,
                                            __nv_bfloat16* __restrict__ Wlo,
                                            int Kdim, int Ndim, int ldout,
                                            int kb, int nb) {
    __shared__ float tl[32][33];
    const int k0 = kb * 32, n0 = nb * 32;
    const int tx = threadIdx.x & 31, ty = threadIdx.x >> 5;
#pragma unroll
    for (int j = 0; j < 4; j++) {
        int k = k0 + ty + j * 8;
        int n = n0 + tx;
        tl[ty + j * 8][tx] = (k < Kdim && n < Ndim) ? W[(size_t)k * Ndim + n] : 0.f;
    }
    __syncthreads();
#pragma unroll
    for (int j = 0; j < 4; j++) {
        int n = n0 + ty + j * 8;
        int k = k0 + tx;
        if (n < Ndim && k < Kdim) {
            __nv_bfloat16 h, l;
            split_bf16(tl[tx][ty + j * 8], h, l);
            Whi[(size_t)n * ldout + k] = h;
            Wlo[(size_t)n * ldout + k] = l;
        }
    }
}

#define PREP_XBLK (ML*DM/1024)     // 1536
__global__ __launch_bounds__(256)
void prep_all_kernel(const float* __restrict__ x, const float* __restrict__ W_in,
                     const float* __restrict__ W_out, const float* __restrict__ W_x,
                     const float* __restrict__ W_delta) {
    int blk = blockIdx.x;
    if (blk < PREP_XBLK) {
        const int i4 = blk * 256 + threadIdx.x;
        float4 v = ((const float4*)x)[i4];
        __nv_bfloat16 h0, l0, h1, l1, h2, l2, h3, l3;
        split_bf16(v.x, h0, l0); split_bf16(v.y, h1, l1);
        split_bf16(v.z, h2, l2); split_bf16(v.w, h3, l3);
        __nv_bfloat162* ph = (__nv_bfloat162*)g_xhi;
        __nv_bfloat162* pl = (__nv_bfloat162*)g_xlo;
        ph[i4 * 2]     = __nv_bfloat162(h0, h1);
        ph[i4 * 2 + 1] = __nv_bfloat162(h2, h3);
        pl[i4 * 2]     = __nv_bfloat162(l0, l1);
        pl[i4 * 2 + 1] = __nv_bfloat162(l2, l3);
        return;
    }
    blk -= PREP_XBLK;
    if (blk < 1152) { wtrans_tile(W_in, g_wihi, g_wilo, DM, 2 * DM, DM, blk % 24, blk / 24); return; }
    blk -= 1152;
    if (blk < 576)  { wtrans_tile(W_out, g_wohi, g_wolo, DM, DM, DM, blk % 24, blk / 24); return; }
    blk -= 576;
    if (blk < 72)   { wtrans_tile(W_x, g_wxhi, g_wxlo, DM, XPW, DM, blk % 24, blk / 24); return; }
    blk -= 72;
    wtrans_tile(W_delta, g_wdhi, g_wdlo, DR, DM, 64, blk % 2, blk / 2);
}
#define PREP_BLKS (PREP_XBLK + 1152 + 576 + 72 + 48)

// ---------------------------------------------------------------------------
// Depthwise causal conv + bias + SiLU -> u (+ bf16 split)
// ---------------------------------------------------------------------------
__global__ __launch_bounds__(256)
void conv_silu_kernel(const float* __restrict__ conv_w, const float* __restrict__ conv_b) {
    int idx = blockIdx.x * blockDim.x + threadIdx.x;
    if (idx >= ML * DM) return;
    int d = idx % DM;
    int t = (idx / DM) % LL;
    int base = idx - t * DM - d;
    float acc = conv_b[d];
#pragma unroll
    for (int k = 0; k < KC; k++) {
        int tt = t - (KC - 1) + k;
        if (tt >= 0)
            acc = fmaf(conv_w[d * KC + k], g_xs0[base + tt * DM + d], acc);
    }
    float u = silu_f(acc);
    g_u[idx] = u;
    split_bf16(u, g_uhi[idx], g_ulo[idx]);
}

// ---------------------------------------------------------------------------
// Transpose fwd: delta, delta*u -> (b,d,t)
// ---------------------------------------------------------------------------
__global__ __launch_bounds__(256)
void trans_fwd_kernel() {
    __shared__ float t0[32][33];
    __shared__ float t1[32][33];
    const int r0 = blockIdx.x * 32, d0 = blockIdx.y * 32;
    const int b = r0 / LL, tb = r0 % LL;
#pragma unroll
    for (int j = 0; j < 4; j++) {
        int row = r0 + threadIdx.y + j * 8;
        int d = d0 + threadIdx.x;
        float dl = g_delta[(size_t)row * DM + d];
        float uu = g_u[(size_t)row * DM + d];
        t0[threadIdx.y + j * 8][threadIdx.x] = dl;
        t1[threadIdx.y + j * 8][threadIdx.x] = dl * uu;
    }
    __syncthreads();
#pragma unroll
    for (int j = 0; j < 4; j++) {
        int d = d0 + threadIdx.y + j * 8;
        int t = tb + threadIdx.x;
        g_deltaT[((size_t)b * DM + d) * LL + t] = t0[threadIdx.x][threadIdx.y + j * 8];
        g_duT   [((size_t)b * DM + d) * LL + t] = t1[threadIdx.x][threadIdx.y + j * 8];
    }
}

// ---------------------------------------------------------------------------
// Parallel selective scan. One block per (b,d).
// ---------------------------------------------------------------------------
__global__ __launch_bounds__(256)
void scan_par_kernel(const float* __restrict__ A_log) {
    __shared__ float pd[LL];
    __shared__ float du[LL];
    __shared__ float ysw[8][LL];
    __shared__ float wsum[9];
    const int bd = blockIdx.x;
    const int b = bd / DM, d = bd - b * DM;
    const int tid = threadIdx.x, lane = tid & 31, wrp = tid >> 5;
    const float* dT  = g_deltaT + (size_t)bd * LL;
    const float* duT = g_duT    + (size_t)bd * LL;

    float4 v = ((const float4*)dT)[tid];
    ((float4*)du)[tid] = ((const float4*)duT)[tid];
    float s0 = v.x, s1 = s0 + v.y, s2 = s1 + v.z, s3 = s2 + v.w;
    float ts = s3;
#pragma unroll
    for (int o = 1; o < 32; o <<= 1) {
        float nv = __shfl_up_sync(0xffffffffu, ts, o);
        if (lane >= o) ts += nv;
    }
    if (lane == 31) wsum[wrp] = ts;
    __syncthreads();
    if (tid == 0) {
        float a = 0.f;
#pragma unroll
        for (int i = 0; i < 8; i++) { float x = wsum[i]; wsum[i] = a; a += x; }
        wsum[8] = a;
    }
    __syncthreads();
    float base = wsum[wrp] + ts - s3;
    pd[tid * 4 + 0] = base + s0;
    pd[tid * 4 + 1] = base + s1;
    pd[tid * 4 + 2] = base + s2;
    pd[tid * 4 + 3] = base + s3;
    const float S = wsum[8];
    __syncthreads();

    const int n0 = wrp, n1 = wrp + 8;
    const float An0 = -__expf(A_log[d * NS + n0]);
    const float An1 = -__expf(A_log[d * NS + n1]);
    const float* B0p = g_bcT + ((size_t)b * 2 * NS + n0) * LL;
    const float* C0p = g_bcT + ((size_t)b * 2 * NS + NS + n0) * LL;
    const float* B1p = g_bcT + ((size_t)b * 2 * NS + n1) * LL;
    const float* C1p = g_bcT + ((size_t)b * 2 * NS + NS + n1) * LL;
    float carry0 = 0.f, carry1 = 0.f;

#pragma unroll
    for (int j = 0; j < 8; j++) {
        const int t = j * 128 + lane * 4;
        float dv[4], pv[4], b0[4], c0[4], b1[4], c1[4];
        *(float4*)dv = *(const float4*)&du[t];
        *(float4*)pv = *(const float4*)&pd[t];
        *(float4*)b0 = *(const float4*)&B0p[t];
        *(float4*)c0 = *(const float4*)&C0p[t];
        *(float4*)b1 = *(const float4*)&B1p[t];
        *(float4*)c1 = *(const float4*)&C1p[t];

        float e0[4], e1[4], p0[4], p1[4];
#pragma unroll
        for (int q = 0; q < 4; q++) {
            e0[q] = __expf(An0 * (S - pv[q]));
            e1[q] = __expf(An1 * (S - pv[q]));
            float z0 = dv[q] * b0[q] * e0[q];
            float z1 = dv[q] * b1[q] * e1[q];
            p0[q] = q ? (p0[q - 1] + z0) : z0;
            p1[q] = q ? (p1[q - 1] + z1) : z1;
        }
        float t0 = p0[3], t1 = p1[3];
#pragma unroll
        for (int o = 1; o < 32; o <<= 1) {
            float a0 = __shfl_up_sync(0xffffffffu, t0, o);
            float a1 = __shfl_up_sync(0xffffffffu, t1, o);
            if (lane >= o) { t0 += a0; t1 += a1; }
        }
        const float bs0 = carry0 + t0 - p0[3];
        const float bs1 = carry1 + t1 - p1[3];
        carry0 += __shfl_sync(0xffffffffu, t0, 31);
        carry1 += __shfl_sync(0xffffffffu, t1, 31);

        float acc4[4];
#pragma unroll
        for (int q = 0; q < 4; q++) {
            float x0 = (bs0 + p0[q]) / (e0[q] + 1e-12f);
            float x1 = (bs1 + p1[q]) / (e1[q] + 1e-12f);
            acc4[q] = x0 * c0[q] + x1 * c1[q];
        }
        *(float4*)&ysw[wrp][t] = *(const float4*)acc4;
    }
    __syncthreads();

    float4 r = ((const float4*)ysw[0])[tid];
#pragma unroll
    for (int w = 1; w < 8; w++) {
        float4 q = ((const float4*)ysw[w])[tid];
        r.x += q.x; r.y += q.y; r.z += q.z; r.w += q.w;
    }
    ((float4*)(g_yT + (size_t)bd * LL))[tid] = r;
}

// ---------------------------------------------------------------------------
// Transpose back + gate + bf16 split of y
// ---------------------------------------------------------------------------
__global__ __launch_bounds__(256)
void back_gate_kernel(const float* __restrict__ D_param) {
    __shared__ float tl[32][33];
    const int r0 = blockIdx.x * 32, d0 = blockIdx.y * 32;
    const int b = r0 / LL, tb = r0 % LL;
#pragma unroll
    for (int j = 0; j < 4; j++) {
        int d = d0 + threadIdx.y + j * 8;
        tl[threadIdx.y + j * 8][threadIdx.x] =
            g_yT[((size_t)b * DM + d) * LL + tb + threadIdx.x];
    }
    __syncthreads();
#pragma unroll
    for (int j = 0; j < 4; j++) {
        int row = r0 + threadIdx.y + j * 8;
        int d = d0 + threadIdx.x;
        float v = tl[threadIdx.x][threadIdx.y + j * 8];
        float uu = g_u[(size_t)row * DM + d];
        float sr = g_sres[(size_t)row * DM + d];
        float y = (v + uu * D_param[d]) * sr;
        __nv_bfloat16 h, l;
        split_bf16(y, h, l);
        g_yhi[(size_t)row * DM + d] = h;
        g_ylo[(size_t)row * DM + d] = l;
    }
}

// ---------------------------------------------------------------------------
extern "C" void kernel_launch(void* const* d_in, const int* in_sizes, int n_in,
                              void* d_out, int out_size) {
    const float* x       = (const float*)d_in[0];
    const float* W_in    = (const float*)d_in[1];
    const float* conv_w  = (const float*)d_in[2];
    const float* conv_b  = (const float*)d_in[3];
    const float* W_x     = (const float*)d_in[4];
    const float* W_delta = (const float*)d_in[5];
    const float* b_delta = (const float*)d_in[6];
    const float* A_log   = (const float*)d_in[7];
    const float* D_param = (const float*)d_in[8];
    const float* W_out   = (const float*)d_in[9];
    float* out = (float*)d_out;

    cudaFuncSetAttribute(hgemm<0>, cudaFuncAttributeMaxDynamicSharedMemorySize, HG_SMEM);
    cudaFuncSetAttribute(hgemm<1>, cudaFuncAttributeMaxDynamicSharedMemorySize, HG_SMEM);
    cudaFuncSetAttribute(hgemm<2>, cudaFuncAttributeMaxDynamicSharedMemorySize, HG_SMEM);
    cudaFuncSetAttribute(hgemm<4>, cudaFuncAttributeMaxDynamicSharedMemorySize, HG_SMEM);

    float *p_delta, *p_xpp;
    cudaGetSymbolAddress((void**)&p_delta, g_delta);
    cudaGetSymbolAddress((void**)&p_xpp,   g_xpp);
    __nv_bfloat16 *p_xhi, *p_xlo, *p_uhi, *p_ulo, *p_yhi, *p_ylo, *p_xphi, *p_xplo;
    __nv_bfloat16 *p_wihi, *p_wilo, *p_wohi, *p_wolo, *p_wxhi, *p_wxlo, *p_wdhi, *p_wdlo;
    cudaGetSymbolAddress((void**)&p_xhi, g_xhi);
    cudaGetSymbolAddress((void**)&p_xlo, g_xlo);
    cudaGetSymbolAddress((void**)&p_uhi, g_uhi);
    cudaGetSymbolAddress((void**)&p_ulo, g_ulo);
    cudaGetSymbolAddress((void**)&p_yhi, g_yhi);
    cudaGetSymbolAddress((void**)&p_ylo, g_ylo);
    cudaGetSymbolAddress((void**)&p_xphi, g_xphi);
    cudaGetSymbolAddress((void**)&p_xplo, g_xplo);
    cudaGetSymbolAddress((void**)&p_wihi, g_wihi);
    cudaGetSymbolAddress((void**)&p_wilo, g_wilo);
    cudaGetSymbolAddress((void**)&p_wohi, g_wohi);
    cudaGetSymbolAddress((void**)&p_wolo, g_wolo);
    cudaGetSymbolAddress((void**)&p_wxhi, g_wxhi);
    cudaGetSymbolAddress((void**)&p_wxlo, g_wxlo);
    cudaGetSymbolAddress((void**)&p_wdhi, g_wdhi);
    cudaGetSymbolAddress((void**)&p_wdlo, g_wdlo);

    // 0) all prep in one launch
    prep_all_kernel<<<PREP_BLKS, 256>>>(x, W_in, W_out, W_x, W_delta);
    // 1) gemm1: x @ W_in -> xs0 | silu(res)
    hgemm<1><<<dim3(ML / 128, (2 * DM) / 64), 256, HG_SMEM>>>(
        p_xhi, p_xlo, p_wihi, p_wilo, nullptr, nullptr, 2 * DM, DM, 0);
    // 2) conv + silu -> u (+ split)
    conv_silu_kernel<<<(ML * DM + 255) / 256, 256>>>(conv_w, conv_b);
    // 3) gemm_x split-K=6: u @ W_x -> partials
    hgemm<4><<<dim3(ML / 128, 2, XSPL), 256, HG_SMEM>>>(
        p_uhi, p_ulo, p_wxhi, p_wxlo, p_xpp, nullptr, XPW, DM, DM / XSPL);
    // 3b) reduce partials -> xphi/xplo + bcT
    reduce_xp_kernel<<<(ML * XPW) / 256, 256>>>();
    // 4) delta: xp48 @ W_delta (+bias, softplus, clip)
    hgemm<2><<<dim3(ML / 128, DM / 64), 256, HG_SMEM>>>(
        p_xphi, p_xplo, p_wdhi, p_wdlo, p_delta, b_delta, DM, 64, 0);
    // 5) transpose, scan, gate
    trans_fwd_kernel<<<dim3(ML / 32, DM / 32), dim3(32, 8)>>>();
    scan_par_kernel<<<BB * DM, 256>>>(A_log);
    back_gate_kernel<<<dim3(ML / 32, DM / 32), dim3(32, 8)>>>(D_param);
    // 6) out = y @ W_out
    hgemm<0><<<dim3(ML / 128, DM / 64), 256, HG_SMEM>>>(
        p_yhi, p_ylo, p_wohi, p_wolo, out, nullptr, DM, DM, 0);
}